// round 2
// baseline (speedup 1.0000x reference)
#include <cuda_runtime.h>
#include <cuda_bf16.h>
#include <cstdint>
#include <math.h>

// ---------------- problem constants ----------------
#define BB 16
#define SS 1024
#define DD 1024
#define HH 8
#define QKD 128          // q/k width
#define EXPD 2048
#define NROWS (BB*SS)    // 16384
#define EOUT (2*QKD + 2*EXPD)  // 4352

// ---------------- scratch (static device, no allocation) ----------------
__device__ __nv_bfloat16 g_xn[(size_t)NROWS * DD];
__device__ __nv_bfloat16 g_proj[(size_t)NROWS * EOUT];
__device__ __nv_bfloat16 g_concat[(size_t)NROWS * EXPD];   // [0,1024): geglu_local, [1024,2048): attention
__device__ __nv_bfloat16 g_v[(size_t)NROWS * DD];
__device__ __nv_bfloat16 g_wexp[(size_t)EOUT * DD];
__device__ __nv_bfloat16 g_wproj[(size_t)DD * EXPD];

// ---------------- helpers ----------------
__device__ __forceinline__ void mma16816(float d[4], const uint32_t a[4], const uint32_t b[2]) {
    asm volatile(
        "mma.sync.aligned.m16n8k16.row.col.f32.bf16.bf16.f32 "
        "{%0,%1,%2,%3},{%4,%5,%6,%7},{%8,%9},{%0,%1,%2,%3};\n"
        : "+f"(d[0]), "+f"(d[1]), "+f"(d[2]), "+f"(d[3])
        : "r"(a[0]), "r"(a[1]), "r"(a[2]), "r"(a[3]), "r"(b[0]), "r"(b[1]));
}

__device__ __forceinline__ uint32_t packbf(float a, float b) {
    __nv_bfloat162 t = __floats2bfloat162_rn(a, b);
    return *reinterpret_cast<uint32_t*>(&t);
}

// ---------------- fp32 -> bf16 weight convert ----------------
__global__ void cvt_kernel(const float* __restrict__ src, __nv_bfloat16* __restrict__ dst, int n4) {
    int i = blockIdx.x * blockDim.x + threadIdx.x;
    if (i < n4) {
        float4 v = ((const float4*)src)[i];
        __nv_bfloat162* d = (__nv_bfloat162*)(dst + (size_t)i * 4);
        d[0] = __floats2bfloat162_rn(v.x, v.y);
        d[1] = __floats2bfloat162_rn(v.z, v.w);
    }
}

// ---------------- LayerNorm: one block (256 thr) per row ----------------
__global__ __launch_bounds__(256) void ln_kernel(const float* __restrict__ x,
                                                 const float* __restrict__ w,
                                                 __nv_bfloat16* __restrict__ out) {
    int row = blockIdx.x;
    float4 v = ((const float4*)(x + (size_t)row * DD))[threadIdx.x];
    float s = v.x + v.y + v.z + v.w;
    float s2 = v.x * v.x + v.y * v.y + v.z * v.z + v.w * v.w;
#pragma unroll
    for (int o = 16; o; o >>= 1) {
        s += __shfl_xor_sync(0xffffffffu, s, o);
        s2 += __shfl_xor_sync(0xffffffffu, s2, o);
    }
    __shared__ float rs[8], rs2[8];
    int warp = threadIdx.x >> 5, lane = threadIdx.x & 31;
    if (!lane) { rs[warp] = s; rs2[warp] = s2; }
    __syncthreads();
    if (threadIdx.x == 0) {
        float a = 0.f, b = 0.f;
#pragma unroll
        for (int i = 0; i < 8; i++) { a += rs[i]; b += rs2[i]; }
        rs[0] = a; rs2[0] = b;
    }
    __syncthreads();
    float mu = rs[0] * (1.f / DD);
    float var = rs2[0] * (1.f / DD) - mu * mu;
    float r = rsqrtf(var + 1e-5f);
    float4 w4 = ((const float4*)w)[threadIdx.x];
    __nv_bfloat16* op = out + (size_t)row * DD + threadIdx.x * 4;
    *(__nv_bfloat162*)op = __floats2bfloat162_rn((v.x - mu) * r * w4.x, (v.y - mu) * r * w4.y);
    *(__nv_bfloat162*)(op + 2) = __floats2bfloat162_rn((v.z - mu) * r * w4.z, (v.w - mu) * r * w4.w);
}

// ---------------- bf16 GEMM: C[M,N] = A[M,K] * Bw[N,K]^T ----------------
// BM=128, BN=128, BK=32, 256 threads, warps 2x4, warp tile 64x32 (4x4 m16n8k16)
#define GBM 128
#define GBN 128
#define GBK 32
#define GLDT 40

__device__ __forceinline__ void st_tile(__nv_bfloat16* s, int lr, int lc, uint4 r0, uint4 r1) {
    *(uint2*)&s[lr * GLDT + lc] = make_uint2(r0.x, r0.y);
    *(uint2*)&s[lr * GLDT + lc + 4] = make_uint2(r0.z, r0.w);
    *(uint2*)&s[(lr + 64) * GLDT + lc] = make_uint2(r1.x, r1.y);
    *(uint2*)&s[(lr + 64) * GLDT + lc + 4] = make_uint2(r1.z, r1.w);
}

template <int NCOLS, bool RESID>
__global__ __launch_bounds__(256) void gemm_bf16(const __nv_bfloat16* __restrict__ A,
                                                 const __nv_bfloat16* __restrict__ Bw,
                                                 __nv_bfloat16* __restrict__ Cb,
                                                 const float* __restrict__ resid,
                                                 float* __restrict__ Cf,
                                                 int K) {
    __shared__ __nv_bfloat16 As[2][GBM * GLDT];
    __shared__ __nv_bfloat16 Bs[2][GBN * GLDT];
    const int tid = threadIdx.x;
    const int warp = tid >> 5, lane = tid & 31;
    const int gid = lane >> 2, tig = lane & 3;
    const int wm = (warp >> 2) * 64, wn = (warp & 3) * 32;
    const int bm = blockIdx.y, bn = blockIdx.x;
    const int lr = tid >> 2;
    const int lc = (tid & 3) * 8;
    const __nv_bfloat16* Ag = A + ((size_t)(bm * GBM + lr)) * K + lc;
    const __nv_bfloat16* Bg = Bw + ((size_t)(bn * GBN + lr)) * K + lc;
    const size_t rstride = (size_t)64 * K;

    float acc[4][4][4];
#pragma unroll
    for (int i = 0; i < 4; i++)
#pragma unroll
        for (int j = 0; j < 4; j++)
#pragma unroll
            for (int r = 0; r < 4; r++) acc[i][j][r] = 0.f;

    uint4 ra0 = *(const uint4*)Ag;
    uint4 ra1 = *(const uint4*)(Ag + rstride);
    uint4 rb0 = *(const uint4*)Bg;
    uint4 rb1 = *(const uint4*)(Bg + rstride);
    st_tile(As[0], lr, lc, ra0, ra1);
    st_tile(Bs[0], lr, lc, rb0, rb1);
    __syncthreads();

    const int KT = K / GBK;
    for (int kt = 0; kt < KT; kt++) {
        int cur = kt & 1;
        if (kt + 1 < KT) {
            const __nv_bfloat16* ap = Ag + (kt + 1) * GBK;
            const __nv_bfloat16* bp = Bg + (kt + 1) * GBK;
            ra0 = *(const uint4*)ap;
            ra1 = *(const uint4*)(ap + rstride);
            rb0 = *(const uint4*)bp;
            rb1 = *(const uint4*)(bp + rstride);
        }
#pragma unroll
        for (int ks = 0; ks < 2; ks++) {
            uint32_t af[4][4], bfr[4][2];
#pragma unroll
            for (int mi = 0; mi < 4; mi++) {
                const __nv_bfloat16* p = &As[cur][(wm + mi * 16 + gid) * GLDT + ks * 16 + tig * 2];
                af[mi][0] = *(const uint32_t*)p;
                af[mi][1] = *(const uint32_t*)(p + 8 * GLDT);
                af[mi][2] = *(const uint32_t*)(p + 8);
                af[mi][3] = *(const uint32_t*)(p + 8 * GLDT + 8);
            }
#pragma unroll
            for (int ni = 0; ni < 4; ni++) {
                const __nv_bfloat16* p = &Bs[cur][(wn + ni * 8 + gid) * GLDT + ks * 16 + tig * 2];
                bfr[ni][0] = *(const uint32_t*)p;
                bfr[ni][1] = *(const uint32_t*)(p + 8);
            }
#pragma unroll
            for (int mi = 0; mi < 4; mi++)
#pragma unroll
                for (int ni = 0; ni < 4; ni++) mma16816(acc[mi][ni], af[mi], bfr[ni]);
        }
        if (kt + 1 < KT) {
            st_tile(As[cur ^ 1], lr, lc, ra0, ra1);
            st_tile(Bs[cur ^ 1], lr, lc, rb0, rb1);
        }
        __syncthreads();
    }

#pragma unroll
    for (int mi = 0; mi < 4; mi++) {
        int r0 = bm * GBM + wm + mi * 16 + gid;
#pragma unroll
        for (int ni = 0; ni < 4; ni++) {
            int col = bn * GBN + wn + ni * 8 + tig * 2;
            size_t i0 = (size_t)r0 * NCOLS + col;
            size_t i1 = (size_t)(r0 + 8) * NCOLS + col;
            if (!RESID) {
                *(__nv_bfloat162*)&Cb[i0] = __floats2bfloat162_rn(acc[mi][ni][0], acc[mi][ni][1]);
                *(__nv_bfloat162*)&Cb[i1] = __floats2bfloat162_rn(acc[mi][ni][2], acc[mi][ni][3]);
            } else {
                float2 v0 = make_float2(acc[mi][ni][0] + resid[i0], acc[mi][ni][1] + resid[i0 + 1]);
                float2 v1 = make_float2(acc[mi][ni][2] + resid[i1], acc[mi][ni][3] + resid[i1 + 1]);
                *(float2*)&Cf[i0] = v0;
                *(float2*)&Cf[i1] = v1;
            }
        }
    }
}

// ---------------- GeGLU ----------------
__global__ __launch_bounds__(256) void geglu_kernel(const __nv_bfloat16* __restrict__ proj,
                                                    __nv_bfloat16* __restrict__ concat,
                                                    __nv_bfloat16* __restrict__ vbuf) {
    int i = blockIdx.x * blockDim.x + threadIdx.x;  // over NROWS * (EXPD/2)
    int row = i >> 10;
    int col = (i & 1023) * 2;
    const size_t pb = (size_t)row * EOUT;
    __nv_bfloat162 l2 = *(const __nv_bfloat162*)&proj[pb + 2 * QKD + col];
    __nv_bfloat162 p2 = *(const __nv_bfloat162*)&proj[pb + 2 * QKD + EXPD + col];
    float p0 = __bfloat162float(p2.x), p1 = __bfloat162float(p2.y);
    float g0 = __bfloat162float(l2.x) * 0.5f * p0 * (1.f + erff(p0 * 0.70710678118654752f));
    float g1 = __bfloat162float(l2.y) * 0.5f * p1 * (1.f + erff(p1 * 0.70710678118654752f));
    __nv_bfloat162 o = __floats2bfloat162_rn(g0, g1);
    if (col < 1024)
        *(__nv_bfloat162*)&concat[(size_t)row * EXPD + col] = o;
    else
        *(__nv_bfloat162*)&vbuf[(size_t)row * DD + col - 1024] = o;
}

// ---------------- flash attention (mma, online softmax) ----------------
// grid (8 q-chunks, B*H); block 256 (8 warps x 16 q rows)
__global__ __launch_bounds__(256, 1) void attn_kernel(const __nv_bfloat16* __restrict__ proj,
                                                      const __nv_bfloat16* __restrict__ vbuf,
                                                      __nv_bfloat16* __restrict__ concat,
                                                      const float* __restrict__ pbm_p,
                                                      const int* __restrict__ fi_p,
                                                      const int* __restrict__ li_p) {
    __shared__ __nv_bfloat16 Ks[128][20];
    __shared__ __nv_bfloat16 Vt[128][136];
    const int tid = threadIdx.x, warp = tid >> 5, lane = tid & 31;
    const int gid = lane >> 2, tig = lane & 3;
    const int bh = blockIdx.y, b = bh >> 3, h = bh & 7;
    const int qbase = blockIdx.x * 128;
    float pbm = *pbm_p;
    const float sp = fmaxf(pbm, 0.f) + log1pf(expf(-fabsf(pbm)));
    int fi = *fi_p; if (fi >= SS) fi = 0;
    int li = *li_p; if (li >= SS) li = 0;

    const int i0 = qbase + warp * 16 + gid;
    const int i1 = i0 + 8;
    uint32_t qa[4];
    {
        const size_t base = ((size_t)(b * SS + i0)) * EOUT + h * 16 + tig * 2;
        qa[0] = *(const uint32_t*)&proj[base];
        qa[1] = *(const uint32_t*)&proj[base + (size_t)8 * EOUT];
        qa[2] = *(const uint32_t*)&proj[base + 8];
        qa[3] = *(const uint32_t*)&proj[base + (size_t)8 * EOUT + 8];
    }
    float m0 = -1e30f, m1 = -1e30f, l0 = 0.f, l1 = 0.f;
    float o[16][4];
#pragma unroll
    for (int ni = 0; ni < 16; ni++)
#pragma unroll
        for (int r = 0; r < 4; r++) o[ni][r] = 0.f;

    const float scale = 0.25f;  // 1/sqrt(16)
    const int qmax = qbase + 127;

    for (int kc = 0; kc < SS / 128; kc++) {
        const int kmin = kc * 128;
        if (kmin > qmax && !((qmax >= fi) && (kmin + 127 >= li))) continue;  // uniform per block

        {  // K chunk -> smem [key][16]
            int r = tid >> 1, c = (tid & 1) * 8;
            const uint4 kv = *(const uint4*)&proj[((size_t)(b * SS + kmin + r)) * EOUT + QKD + h * 16 + c];
            *(uint2*)&Ks[r][c] = make_uint2(kv.x, kv.y);
            *(uint2*)&Ks[r][c + 4] = make_uint2(kv.z, kv.w);
        }
        {  // V chunk transposed -> smem [dv][key]
            int d2 = (tid & 63) * 2, r0 = tid >> 6;
            const size_t gb = ((size_t)(b * SS + kmin)) * DD + h * 128 + d2;
#pragma unroll
            for (int j = 0; j < 32; j++) {
                int r = r0 + j * 4;
                __nv_bfloat162 vv = *(const __nv_bfloat162*)&vbuf[gb + (size_t)r * DD];
                Vt[d2][r] = vv.x;
                Vt[d2 + 1][r] = vv.y;
            }
        }
        __syncthreads();

        float sc[16][4];
#pragma unroll
        for (int ni = 0; ni < 16; ni++) {
            sc[ni][0] = sc[ni][1] = sc[ni][2] = sc[ni][3] = 0.f;
            uint32_t bfr[2];
            bfr[0] = *(const uint32_t*)&Ks[ni * 8 + gid][tig * 2];
            bfr[1] = *(const uint32_t*)&Ks[ni * 8 + gid][tig * 2 + 8];
            mma16816(sc[ni], qa, bfr);
        }
        float rmax0 = -1e30f, rmax1 = -1e30f;
#pragma unroll
        for (int ni = 0; ni < 16; ni++) {
            int jc = kmin + ni * 8 + tig * 2;
#pragma unroll
            for (int r = 0; r < 4; r++) {
                int j = jc + (r & 1);
                int i = (r < 2) ? i0 : i1;
                bool ok = (j <= i) || ((i >= fi) && (j >= li));
                float s = ok ? fmaf(sc[ni][r], scale, sp * (float)(j - i)) : -1e30f;
                sc[ni][r] = s;
                if (r < 2) rmax0 = fmaxf(rmax0, s);
                else rmax1 = fmaxf(rmax1, s);
            }
        }
        rmax0 = fmaxf(rmax0, __shfl_xor_sync(0xffffffffu, rmax0, 1));
        rmax0 = fmaxf(rmax0, __shfl_xor_sync(0xffffffffu, rmax0, 2));
        rmax1 = fmaxf(rmax1, __shfl_xor_sync(0xffffffffu, rmax1, 1));
        rmax1 = fmaxf(rmax1, __shfl_xor_sync(0xffffffffu, rmax1, 2));
        float mn0 = fmaxf(m0, rmax0), mn1 = fmaxf(m1, rmax1);
        float cor0 = __expf(m0 - mn0), cor1 = __expf(m1 - mn1);
        m0 = mn0; m1 = mn1;
        float rs0 = 0.f, rs1 = 0.f;
#pragma unroll
        for (int ni = 0; ni < 16; ni++) {
            sc[ni][0] = __expf(sc[ni][0] - m0); rs0 += sc[ni][0];
            sc[ni][1] = __expf(sc[ni][1] - m0); rs0 += sc[ni][1];
            sc[ni][2] = __expf(sc[ni][2] - m1); rs1 += sc[ni][2];
            sc[ni][3] = __expf(sc[ni][3] - m1); rs1 += sc[ni][3];
        }
        rs0 += __shfl_xor_sync(0xffffffffu, rs0, 1);
        rs0 += __shfl_xor_sync(0xffffffffu, rs0, 2);
        rs1 += __shfl_xor_sync(0xffffffffu, rs1, 1);
        rs1 += __shfl_xor_sync(0xffffffffu, rs1, 2);
        l0 = l0 * cor0 + rs0;
        l1 = l1 * cor1 + rs1;
#pragma unroll
        for (int ni = 0; ni < 16; ni++) {
            o[ni][0] *= cor0; o[ni][1] *= cor0; o[ni][2] *= cor1; o[ni][3] *= cor1;
        }
#pragma unroll
        for (int ks = 0; ks < 8; ks++) {
            uint32_t pa[4];
            pa[0] = packbf(sc[2 * ks][0], sc[2 * ks][1]);
            pa[1] = packbf(sc[2 * ks][2], sc[2 * ks][3]);
            pa[2] = packbf(sc[2 * ks + 1][0], sc[2 * ks + 1][1]);
            pa[3] = packbf(sc[2 * ks + 1][2], sc[2 * ks + 1][3]);
#pragma unroll
            for (int ni = 0; ni < 16; ni++) {
                uint32_t vb[2];
                const __nv_bfloat16* p = &Vt[ni * 8 + gid][ks * 16 + tig * 2];
                vb[0] = *(const uint32_t*)p;
                vb[1] = *(const uint32_t*)(p + 8);
                mma16816(o[ni], pa, vb);
            }
        }
        __syncthreads();
    }

    float inv0 = 1.f / l0, inv1 = 1.f / l1;
#pragma unroll
    for (int ni = 0; ni < 16; ni++) {
        int col = 1024 + h * 128 + ni * 8 + tig * 2;
        *(__nv_bfloat162*)&concat[((size_t)(b * SS) + i0) * EXPD + col] =
            __floats2bfloat162_rn(o[ni][0] * inv0, o[ni][1] * inv0);
        *(__nv_bfloat162*)&concat[((size_t)(b * SS) + i1) * EXPD + col] =
            __floats2bfloat162_rn(o[ni][2] * inv1, o[ni][3] * inv1);
    }
}

// ---------------- launch ----------------
extern "C" void kernel_launch(void* const* d_in, const int* in_sizes, int n_in,
                              void* d_out, int out_size) {
    const float* x = (const float*)d_in[0];
    const float* norm_w = (const float*)d_in[1];
    const float* expand_w = (const float*)d_in[2];
    const float* project_w = (const float*)d_in[3];
    const float* pbm = (const float*)d_in[4];
    const int* fi = (const int*)d_in[5];
    const int* li = (const int*)d_in[6];
    float* out = (float*)d_out;

    void *p_xn, *p_proj, *p_concat, *p_v, *p_wexp, *p_wproj;
    cudaGetSymbolAddress(&p_xn, g_xn);
    cudaGetSymbolAddress(&p_proj, g_proj);
    cudaGetSymbolAddress(&p_concat, g_concat);
    cudaGetSymbolAddress(&p_v, g_v);
    cudaGetSymbolAddress(&p_wexp, g_wexp);
    cudaGetSymbolAddress(&p_wproj, g_wproj);
    __nv_bfloat16* xn = (__nv_bfloat16*)p_xn;
    __nv_bfloat16* proj = (__nv_bfloat16*)p_proj;
    __nv_bfloat16* concat = (__nv_bfloat16*)p_concat;
    __nv_bfloat16* vb = (__nv_bfloat16*)p_v;
    __nv_bfloat16* wexp = (__nv_bfloat16*)p_wexp;
    __nv_bfloat16* wproj = (__nv_bfloat16*)p_wproj;

    // weights -> bf16
    cvt_kernel<<<(EOUT * DD / 4 + 255) / 256, 256>>>(expand_w, wexp, EOUT * DD / 4);
    cvt_kernel<<<(DD * EXPD / 4 + 255) / 256, 256>>>(project_w, wproj, DD * EXPD / 4);

    // layernorm
    ln_kernel<<<NROWS, 256>>>(x, norm_w, xn);

    // expand GEMM: proj[16384,4352] = xn[16384,1024] @ wexp[4352,1024]^T
    gemm_bf16<EOUT, false><<<dim3(EOUT / GBN, NROWS / GBM), 256>>>(xn, wexp, proj, nullptr, nullptr, DD);

    // geglu -> concat[:, :1024] and v buffer
    geglu_kernel<<<NROWS * (EXPD / 2) / 256, 256>>>(proj, concat, vb);

    // attention -> concat[:, 1024:2048]
    attn_kernel<<<dim3(SS / 128, BB * HH), 256>>>(proj, vb, concat, pbm, fi, li);

    // project GEMM + residual: out[16384,1024] = concat[16384,2048] @ wproj[1024,2048]^T + x
    gemm_bf16<DD, true><<<dim3(DD / GBN, NROWS / GBM), 256>>>(concat, wproj, nullptr, x, out, EXPD);
}

// round 3
// speedup vs baseline: 1.0042x; 1.0042x over previous
#include <cuda_runtime.h>
#include <cuda_bf16.h>
#include <cstdint>
#include <math.h>

// ---------------- problem constants ----------------
#define BB 16
#define SS 1024
#define DD 1024
#define HH 8
#define QKD 128          // q/k width
#define EXPD 2048
#define NROWS (BB*SS)    // 16384
#define EOUT (2*QKD + 2*EXPD)  // 4352

// ---------------- scratch (static device, no allocation) ----------------
__device__ __nv_bfloat16 g_xn[(size_t)NROWS * DD];
__device__ __nv_bfloat16 g_proj[(size_t)NROWS * EOUT];
__device__ __nv_bfloat16 g_concat[(size_t)NROWS * EXPD];   // [0,1024): geglu_local, [1024,2048): attention
__device__ __nv_bfloat16 g_v[(size_t)NROWS * DD];
__device__ __nv_bfloat16 g_wexp[(size_t)EOUT * DD];
__device__ __nv_bfloat16 g_wproj[(size_t)DD * EXPD];

// ---------------- helpers ----------------
__device__ __forceinline__ void mma16816(float d[4], const uint32_t a[4], const uint32_t b[2]) {
    asm volatile(
        "mma.sync.aligned.m16n8k16.row.col.f32.bf16.bf16.f32 "
        "{%0,%1,%2,%3},{%4,%5,%6,%7},{%8,%9},{%0,%1,%2,%3};\n"
        : "+f"(d[0]), "+f"(d[1]), "+f"(d[2]), "+f"(d[3])
        : "r"(a[0]), "r"(a[1]), "r"(a[2]), "r"(a[3]), "r"(b[0]), "r"(b[1]));
}

__device__ __forceinline__ uint32_t packbf(float a, float b) {
    __nv_bfloat162 t = __floats2bfloat162_rn(a, b);
    return *reinterpret_cast<uint32_t*>(&t);
}

// ---------------- fp32 -> bf16 weight convert ----------------
__global__ void cvt_kernel(const float* __restrict__ src, __nv_bfloat16* __restrict__ dst, int n4) {
    int i = blockIdx.x * blockDim.x + threadIdx.x;
    if (i < n4) {
        float4 v = ((const float4*)src)[i];
        __nv_bfloat162* d = (__nv_bfloat162*)(dst + (size_t)i * 4);
        d[0] = __floats2bfloat162_rn(v.x, v.y);
        d[1] = __floats2bfloat162_rn(v.z, v.w);
    }
}

// ---------------- LayerNorm: one block (256 thr) per row ----------------
__global__ __launch_bounds__(256) void ln_kernel(const float* __restrict__ x,
                                                 const float* __restrict__ w,
                                                 __nv_bfloat16* __restrict__ out) {
    int row = blockIdx.x;
    float4 v = ((const float4*)(x + (size_t)row * DD))[threadIdx.x];
    float s = v.x + v.y + v.z + v.w;
    float s2 = v.x * v.x + v.y * v.y + v.z * v.z + v.w * v.w;
#pragma unroll
    for (int o = 16; o; o >>= 1) {
        s += __shfl_xor_sync(0xffffffffu, s, o);
        s2 += __shfl_xor_sync(0xffffffffu, s2, o);
    }
    __shared__ float rs[8], rs2[8];
    int warp = threadIdx.x >> 5, lane = threadIdx.x & 31;
    if (!lane) { rs[warp] = s; rs2[warp] = s2; }
    __syncthreads();
    if (threadIdx.x == 0) {
        float a = 0.f, b = 0.f;
#pragma unroll
        for (int i = 0; i < 8; i++) { a += rs[i]; b += rs2[i]; }
        rs[0] = a; rs2[0] = b;
    }
    __syncthreads();
    float mu = rs[0] * (1.f / DD);
    float var = rs2[0] * (1.f / DD) - mu * mu;
    float r = rsqrtf(var + 1e-5f);
    float4 w4 = ((const float4*)w)[threadIdx.x];
    __nv_bfloat16* op = out + (size_t)row * DD + threadIdx.x * 4;
    *(__nv_bfloat162*)op = __floats2bfloat162_rn((v.x - mu) * r * w4.x, (v.y - mu) * r * w4.y);
    *(__nv_bfloat162*)(op + 2) = __floats2bfloat162_rn((v.z - mu) * r * w4.z, (v.w - mu) * r * w4.w);
}

// ---------------- bf16 GEMM: C[M,N] = A[M,K] * Bw[N,K]^T ----------------
// BM=128, BN=128, BK=32, 256 threads, warps 2x4, warp tile 64x32 (4x4 m16n8k16)
#define GBM 128
#define GBN 128
#define GBK 32
#define GLDT 40

__device__ __forceinline__ void st_tile(__nv_bfloat16* s, int lr, int lc, uint4 r0, uint4 r1) {
    *(uint2*)&s[lr * GLDT + lc] = make_uint2(r0.x, r0.y);
    *(uint2*)&s[lr * GLDT + lc + 4] = make_uint2(r0.z, r0.w);
    *(uint2*)&s[(lr + 64) * GLDT + lc] = make_uint2(r1.x, r1.y);
    *(uint2*)&s[(lr + 64) * GLDT + lc + 4] = make_uint2(r1.z, r1.w);
}

template <int NCOLS, bool RESID>
__global__ __launch_bounds__(256) void gemm_bf16(const __nv_bfloat16* __restrict__ A,
                                                 const __nv_bfloat16* __restrict__ Bw,
                                                 __nv_bfloat16* __restrict__ Cb,
                                                 const float* __restrict__ resid,
                                                 float* __restrict__ Cf,
                                                 int K) {
    __shared__ __nv_bfloat16 As[2][GBM * GLDT];
    __shared__ __nv_bfloat16 Bs[2][GBN * GLDT];
    const int tid = threadIdx.x;
    const int warp = tid >> 5, lane = tid & 31;
    const int gid = lane >> 2, tig = lane & 3;
    const int wm = (warp >> 2) * 64, wn = (warp & 3) * 32;
    const int bm = blockIdx.y, bn = blockIdx.x;
    const int lr = tid >> 2;
    const int lc = (tid & 3) * 8;
    const __nv_bfloat16* Ag = A + ((size_t)(bm * GBM + lr)) * K + lc;
    const __nv_bfloat16* Bg = Bw + ((size_t)(bn * GBN + lr)) * K + lc;
    const size_t rstride = (size_t)64 * K;

    float acc[4][4][4];
#pragma unroll
    for (int i = 0; i < 4; i++)
#pragma unroll
        for (int j = 0; j < 4; j++)
#pragma unroll
            for (int r = 0; r < 4; r++) acc[i][j][r] = 0.f;

    uint4 ra0 = *(const uint4*)Ag;
    uint4 ra1 = *(const uint4*)(Ag + rstride);
    uint4 rb0 = *(const uint4*)Bg;
    uint4 rb1 = *(const uint4*)(Bg + rstride);
    st_tile(As[0], lr, lc, ra0, ra1);
    st_tile(Bs[0], lr, lc, rb0, rb1);
    __syncthreads();

    const int KT = K / GBK;
    for (int kt = 0; kt < KT; kt++) {
        int cur = kt & 1;
        if (kt + 1 < KT) {
            const __nv_bfloat16* ap = Ag + (kt + 1) * GBK;
            const __nv_bfloat16* bp = Bg + (kt + 1) * GBK;
            ra0 = *(const uint4*)ap;
            ra1 = *(const uint4*)(ap + rstride);
            rb0 = *(const uint4*)bp;
            rb1 = *(const uint4*)(bp + rstride);
        }
#pragma unroll
        for (int ks = 0; ks < 2; ks++) {
            uint32_t af[4][4], bfr[4][2];
#pragma unroll
            for (int mi = 0; mi < 4; mi++) {
                const __nv_bfloat16* p = &As[cur][(wm + mi * 16 + gid) * GLDT + ks * 16 + tig * 2];
                af[mi][0] = *(const uint32_t*)p;
                af[mi][1] = *(const uint32_t*)(p + 8 * GLDT);
                af[mi][2] = *(const uint32_t*)(p + 8);
                af[mi][3] = *(const uint32_t*)(p + 8 * GLDT + 8);
            }
#pragma unroll
            for (int ni = 0; ni < 4; ni++) {
                const __nv_bfloat16* p = &Bs[cur][(wn + ni * 8 + gid) * GLDT + ks * 16 + tig * 2];
                bfr[ni][0] = *(const uint32_t*)p;
                bfr[ni][1] = *(const uint32_t*)(p + 8);
            }
#pragma unroll
            for (int mi = 0; mi < 4; mi++)
#pragma unroll
                for (int ni = 0; ni < 4; ni++) mma16816(acc[mi][ni], af[mi], bfr[ni]);
        }
        if (kt + 1 < KT) {
            st_tile(As[cur ^ 1], lr, lc, ra0, ra1);
            st_tile(Bs[cur ^ 1], lr, lc, rb0, rb1);
        }
        __syncthreads();
    }

#pragma unroll
    for (int mi = 0; mi < 4; mi++) {
        int r0 = bm * GBM + wm + mi * 16 + gid;
#pragma unroll
        for (int ni = 0; ni < 4; ni++) {
            int col = bn * GBN + wn + ni * 8 + tig * 2;
            size_t i0 = (size_t)r0 * NCOLS + col;
            size_t i1 = (size_t)(r0 + 8) * NCOLS + col;
            if (!RESID) {
                *(__nv_bfloat162*)&Cb[i0] = __floats2bfloat162_rn(acc[mi][ni][0], acc[mi][ni][1]);
                *(__nv_bfloat162*)&Cb[i1] = __floats2bfloat162_rn(acc[mi][ni][2], acc[mi][ni][3]);
            } else {
                float2 v0 = make_float2(acc[mi][ni][0] + resid[i0], acc[mi][ni][1] + resid[i0 + 1]);
                float2 v1 = make_float2(acc[mi][ni][2] + resid[i1], acc[mi][ni][3] + resid[i1 + 1]);
                *(float2*)&Cf[i0] = v0;
                *(float2*)&Cf[i1] = v1;
            }
        }
    }
}

// ---------------- GeGLU ----------------
__global__ __launch_bounds__(256) void geglu_kernel(const __nv_bfloat16* __restrict__ proj,
                                                    __nv_bfloat16* __restrict__ concat,
                                                    __nv_bfloat16* __restrict__ vbuf) {
    int i = blockIdx.x * blockDim.x + threadIdx.x;  // over NROWS * (EXPD/2)
    int row = i >> 10;
    int col = (i & 1023) * 2;
    const size_t pb = (size_t)row * EOUT;
    __nv_bfloat162 l2 = *(const __nv_bfloat162*)&proj[pb + 2 * QKD + col];
    __nv_bfloat162 p2 = *(const __nv_bfloat162*)&proj[pb + 2 * QKD + EXPD + col];
    float p0 = __bfloat162float(p2.x), p1 = __bfloat162float(p2.y);
    float g0 = __bfloat162float(l2.x) * 0.5f * p0 * (1.f + erff(p0 * 0.70710678118654752f));
    float g1 = __bfloat162float(l2.y) * 0.5f * p1 * (1.f + erff(p1 * 0.70710678118654752f));
    __nv_bfloat162 o = __floats2bfloat162_rn(g0, g1);
    if (col < 1024)
        *(__nv_bfloat162*)&concat[(size_t)row * EXPD + col] = o;
    else
        *(__nv_bfloat162*)&vbuf[(size_t)row * DD + col - 1024] = o;
}

// ---------------- flash attention (mma, online softmax) ----------------
// grid (8 q-chunks, B*H); block 256 (8 warps x 16 q rows)
__global__ __launch_bounds__(256, 1) void attn_kernel(const __nv_bfloat16* __restrict__ proj,
                                                      const __nv_bfloat16* __restrict__ vbuf,
                                                      __nv_bfloat16* __restrict__ concat,
                                                      const float* __restrict__ pbm_p,
                                                      const int* __restrict__ fi_p,
                                                      const int* __restrict__ li_p) {
    __shared__ __nv_bfloat16 Ks[128][20];
    __shared__ __nv_bfloat16 Vt[128][136];
    const int tid = threadIdx.x, warp = tid >> 5, lane = tid & 31;
    const int gid = lane >> 2, tig = lane & 3;
    const int bh = blockIdx.y, b = bh >> 3, h = bh & 7;
    const int qbase = blockIdx.x * 128;
    float pbm = *pbm_p;
    const float sp = fmaxf(pbm, 0.f) + log1pf(expf(-fabsf(pbm)));
    int fi = *fi_p; if (fi >= SS) fi = 0;
    int li = *li_p; if (li >= SS) li = 0;

    const int i0 = qbase + warp * 16 + gid;
    const int i1 = i0 + 8;
    uint32_t qa[4];
    {
        const size_t base = ((size_t)(b * SS + i0)) * EOUT + h * 16 + tig * 2;
        qa[0] = *(const uint32_t*)&proj[base];
        qa[1] = *(const uint32_t*)&proj[base + (size_t)8 * EOUT];
        qa[2] = *(const uint32_t*)&proj[base + 8];
        qa[3] = *(const uint32_t*)&proj[base + (size_t)8 * EOUT + 8];
    }
    float m0 = -1e30f, m1 = -1e30f, l0 = 0.f, l1 = 0.f;
    float o[16][4];
#pragma unroll
    for (int ni = 0; ni < 16; ni++)
#pragma unroll
        for (int r = 0; r < 4; r++) o[ni][r] = 0.f;

    const float scale = 0.25f;  // 1/sqrt(16)
    const int qmax = qbase + 127;

    for (int kc = 0; kc < SS / 128; kc++) {
        const int kmin = kc * 128;
        if (kmin > qmax && !((qmax >= fi) && (kmin + 127 >= li))) continue;  // uniform per block

        {  // K chunk -> smem [key][16]
            int r = tid >> 1, c = (tid & 1) * 8;
            const uint4 kv = *(const uint4*)&proj[((size_t)(b * SS + kmin + r)) * EOUT + QKD + h * 16 + c];
            *(uint2*)&Ks[r][c] = make_uint2(kv.x, kv.y);
            *(uint2*)&Ks[r][c + 4] = make_uint2(kv.z, kv.w);
        }
        {  // V chunk transposed -> smem [dv][key]
            int d2 = (tid & 63) * 2, r0 = tid >> 6;
            const size_t gb = ((size_t)(b * SS + kmin)) * DD + h * 128 + d2;
#pragma unroll
            for (int j = 0; j < 32; j++) {
                int r = r0 + j * 4;
                __nv_bfloat162 vv = *(const __nv_bfloat162*)&vbuf[gb + (size_t)r * DD];
                Vt[d2][r] = vv.x;
                Vt[d2 + 1][r] = vv.y;
            }
        }
        __syncthreads();

        float sc[16][4];
#pragma unroll
        for (int ni = 0; ni < 16; ni++) {
            sc[ni][0] = sc[ni][1] = sc[ni][2] = sc[ni][3] = 0.f;
            uint32_t bfr[2];
            bfr[0] = *(const uint32_t*)&Ks[ni * 8 + gid][tig * 2];
            bfr[1] = *(const uint32_t*)&Ks[ni * 8 + gid][tig * 2 + 8];
            mma16816(sc[ni], qa, bfr);
        }
        float rmax0 = -1e30f, rmax1 = -1e30f;
#pragma unroll
        for (int ni = 0; ni < 16; ni++) {
            int jc = kmin + ni * 8 + tig * 2;
#pragma unroll
            for (int r = 0; r < 4; r++) {
                int j = jc + (r & 1);
                int i = (r < 2) ? i0 : i1;
                bool ok = (j <= i) || ((i >= fi) && (j >= li));
                float s = ok ? fmaf(sc[ni][r], scale, sp * (float)(j - i)) : -1e30f;
                sc[ni][r] = s;
                if (r < 2) rmax0 = fmaxf(rmax0, s);
                else rmax1 = fmaxf(rmax1, s);
            }
        }
        rmax0 = fmaxf(rmax0, __shfl_xor_sync(0xffffffffu, rmax0, 1));
        rmax0 = fmaxf(rmax0, __shfl_xor_sync(0xffffffffu, rmax0, 2));
        rmax1 = fmaxf(rmax1, __shfl_xor_sync(0xffffffffu, rmax1, 1));
        rmax1 = fmaxf(rmax1, __shfl_xor_sync(0xffffffffu, rmax1, 2));
        float mn0 = fmaxf(m0, rmax0), mn1 = fmaxf(m1, rmax1);
        float cor0 = __expf(m0 - mn0), cor1 = __expf(m1 - mn1);
        m0 = mn0; m1 = mn1;
        float rs0 = 0.f, rs1 = 0.f;
#pragma unroll
        for (int ni = 0; ni < 16; ni++) {
            sc[ni][0] = __expf(sc[ni][0] - m0); rs0 += sc[ni][0];
            sc[ni][1] = __expf(sc[ni][1] - m0); rs0 += sc[ni][1];
            sc[ni][2] = __expf(sc[ni][2] - m1); rs1 += sc[ni][2];
            sc[ni][3] = __expf(sc[ni][3] - m1); rs1 += sc[ni][3];
        }
        rs0 += __shfl_xor_sync(0xffffffffu, rs0, 1);
        rs0 += __shfl_xor_sync(0xffffffffu, rs0, 2);
        rs1 += __shfl_xor_sync(0xffffffffu, rs1, 1);
        rs1 += __shfl_xor_sync(0xffffffffu, rs1, 2);
        l0 = l0 * cor0 + rs0;
        l1 = l1 * cor1 + rs1;
#pragma unroll
        for (int ni = 0; ni < 16; ni++) {
            o[ni][0] *= cor0; o[ni][1] *= cor0; o[ni][2] *= cor1; o[ni][3] *= cor1;
        }
#pragma unroll
        for (int ks = 0; ks < 8; ks++) {
            uint32_t pa[4];
            pa[0] = packbf(sc[2 * ks][0], sc[2 * ks][1]);
            pa[1] = packbf(sc[2 * ks][2], sc[2 * ks][3]);
            pa[2] = packbf(sc[2 * ks + 1][0], sc[2 * ks + 1][1]);
            pa[3] = packbf(sc[2 * ks + 1][2], sc[2 * ks + 1][3]);
#pragma unroll
            for (int ni = 0; ni < 16; ni++) {
                uint32_t vb[2];
                const __nv_bfloat16* p = &Vt[ni * 8 + gid][ks * 16 + tig * 2];
                vb[0] = *(const uint32_t*)p;
                vb[1] = *(const uint32_t*)(p + 8);
                mma16816(o[ni], pa, vb);
            }
        }
        __syncthreads();
    }

    float inv0 = 1.f / l0, inv1 = 1.f / l1;
#pragma unroll
    for (int ni = 0; ni < 16; ni++) {
        int col = 1024 + h * 128 + ni * 8 + tig * 2;
        *(__nv_bfloat162*)&concat[((size_t)(b * SS) + i0) * EXPD + col] =
            __floats2bfloat162_rn(o[ni][0] * inv0, o[ni][1] * inv0);
        *(__nv_bfloat162*)&concat[((size_t)(b * SS) + i1) * EXPD + col] =
            __floats2bfloat162_rn(o[ni][2] * inv1, o[ni][3] * inv1);
    }
}

// ---------------- launch ----------------
extern "C" void kernel_launch(void* const* d_in, const int* in_sizes, int n_in,
                              void* d_out, int out_size) {
    const float* x = (const float*)d_in[0];
    const float* norm_w = (const float*)d_in[1];
    const float* expand_w = (const float*)d_in[2];
    const float* project_w = (const float*)d_in[3];
    const float* pbm = (const float*)d_in[4];
    const int* fi = (const int*)d_in[5];
    const int* li = (const int*)d_in[6];
    float* out = (float*)d_out;

    void *p_xn, *p_proj, *p_concat, *p_v, *p_wexp, *p_wproj;
    cudaGetSymbolAddress(&p_xn, g_xn);
    cudaGetSymbolAddress(&p_proj, g_proj);
    cudaGetSymbolAddress(&p_concat, g_concat);
    cudaGetSymbolAddress(&p_v, g_v);
    cudaGetSymbolAddress(&p_wexp, g_wexp);
    cudaGetSymbolAddress(&p_wproj, g_wproj);
    __nv_bfloat16* xn = (__nv_bfloat16*)p_xn;
    __nv_bfloat16* proj = (__nv_bfloat16*)p_proj;
    __nv_bfloat16* concat = (__nv_bfloat16*)p_concat;
    __nv_bfloat16* vb = (__nv_bfloat16*)p_v;
    __nv_bfloat16* wexp = (__nv_bfloat16*)p_wexp;
    __nv_bfloat16* wproj = (__nv_bfloat16*)p_wproj;

    // weights -> bf16
    cvt_kernel<<<(EOUT * DD / 4 + 255) / 256, 256>>>(expand_w, wexp, EOUT * DD / 4);
    cvt_kernel<<<(DD * EXPD / 4 + 255) / 256, 256>>>(project_w, wproj, DD * EXPD / 4);

    // layernorm
    ln_kernel<<<NROWS, 256>>>(x, norm_w, xn);

    // expand GEMM: proj[16384,4352] = xn[16384,1024] @ wexp[4352,1024]^T
    gemm_bf16<EOUT, false><<<dim3(EOUT / GBN, NROWS / GBM), 256>>>(xn, wexp, proj, nullptr, nullptr, DD);

    // geglu -> concat[:, :1024] and v buffer
    geglu_kernel<<<NROWS * (EXPD / 2) / 256, 256>>>(proj, concat, vb);

    // attention -> concat[:, 1024:2048]
    attn_kernel<<<dim3(SS / 128, BB * HH), 256>>>(proj, vb, concat, pbm, fi, li);

    // project GEMM + residual: out[16384,1024] = concat[16384,2048] @ wproj[1024,2048]^T + x
    gemm_bf16<DD, true><<<dim3(DD / GBN, NROWS / GBM), 256>>>(concat, wproj, nullptr, x, out, EXPD);
}

// round 4
// speedup vs baseline: 1.0061x; 1.0018x over previous
#include <cuda_runtime.h>
#include <cuda_bf16.h>
#include <cstdint>
#include <math.h>

// ---------------- problem constants ----------------
#define BB 16
#define SS 1024
#define DD 1024
#define HH 8
#define QKD 128          // q/k width
#define EXPD 2048
#define NROWS (BB*SS)    // 16384
#define EOUT (2*QKD + 2*EXPD)  // 4352

// ---------------- scratch (static device, no allocation) ----------------
__device__ __nv_bfloat16 g_xn[(size_t)NROWS * DD];
__device__ __nv_bfloat16 g_proj[(size_t)NROWS * EOUT];
__device__ __nv_bfloat16 g_concat[(size_t)NROWS * EXPD];   // [0,1024): geglu_local, [1024,2048): attention
__device__ __nv_bfloat16 g_v[(size_t)NROWS * DD];
__device__ __nv_bfloat16 g_wexp[(size_t)EOUT * DD];
__device__ __nv_bfloat16 g_wproj[(size_t)DD * EXPD];

// ---------------- helpers ----------------
__device__ __forceinline__ void mma16816(float d[4], const uint32_t a[4], const uint32_t b[2]) {
    asm volatile(
        "mma.sync.aligned.m16n8k16.row.col.f32.bf16.bf16.f32 "
        "{%0,%1,%2,%3},{%4,%5,%6,%7},{%8,%9},{%0,%1,%2,%3};\n"
        : "+f"(d[0]), "+f"(d[1]), "+f"(d[2]), "+f"(d[3])
        : "r"(a[0]), "r"(a[1]), "r"(a[2]), "r"(a[3]), "r"(b[0]), "r"(b[1]));
}

__device__ __forceinline__ uint32_t packbf(float a, float b) {
    __nv_bfloat162 t = __floats2bfloat162_rn(a, b);
    return *reinterpret_cast<uint32_t*>(&t);
}

// ---------------- fp32 -> bf16 weight convert ----------------
__global__ void cvt_kernel(const float* __restrict__ src, __nv_bfloat16* __restrict__ dst, int n4) {
    int i = blockIdx.x * blockDim.x + threadIdx.x;
    if (i < n4) {
        float4 v = ((const float4*)src)[i];
        __nv_bfloat162* d = (__nv_bfloat162*)(dst + (size_t)i * 4);
        d[0] = __floats2bfloat162_rn(v.x, v.y);
        d[1] = __floats2bfloat162_rn(v.z, v.w);
    }
}

// ---------------- LayerNorm: one block (256 thr) per row ----------------
__global__ __launch_bounds__(256) void ln_kernel(const float* __restrict__ x,
                                                 const float* __restrict__ w,
                                                 __nv_bfloat16* __restrict__ out) {
    int row = blockIdx.x;
    float4 v = ((const float4*)(x + (size_t)row * DD))[threadIdx.x];
    float s = v.x + v.y + v.z + v.w;
    float s2 = v.x * v.x + v.y * v.y + v.z * v.z + v.w * v.w;
#pragma unroll
    for (int o = 16; o; o >>= 1) {
        s += __shfl_xor_sync(0xffffffffu, s, o);
        s2 += __shfl_xor_sync(0xffffffffu, s2, o);
    }
    __shared__ float rs[8], rs2[8];
    int warp = threadIdx.x >> 5, lane = threadIdx.x & 31;
    if (!lane) { rs[warp] = s; rs2[warp] = s2; }
    __syncthreads();
    if (threadIdx.x == 0) {
        float a = 0.f, b = 0.f;
#pragma unroll
        for (int i = 0; i < 8; i++) { a += rs[i]; b += rs2[i]; }
        rs[0] = a; rs2[0] = b;
    }
    __syncthreads();
    float mu = rs[0] * (1.f / DD);
    float var = rs2[0] * (1.f / DD) - mu * mu;
    float r = rsqrtf(var + 1e-5f);
    float4 w4 = ((const float4*)w)[threadIdx.x];
    __nv_bfloat16* op = out + (size_t)row * DD + threadIdx.x * 4;
    *(__nv_bfloat162*)op = __floats2bfloat162_rn((v.x - mu) * r * w4.x, (v.y - mu) * r * w4.y);
    *(__nv_bfloat162*)(op + 2) = __floats2bfloat162_rn((v.z - mu) * r * w4.z, (v.w - mu) * r * w4.w);
}

// ---------------- bf16 GEMM: C[M,N] = A[M,K] * Bw[N,K]^T ----------------
// BM=128, BN=128, BK=32, 256 threads, warps 2x4, warp tile 64x32 (4x4 m16n8k16)
#define GBM 128
#define GBN 128
#define GBK 32
#define GLDT 40

__device__ __forceinline__ void st_tile(__nv_bfloat16* s, int lr, int lc, uint4 r0, uint4 r1) {
    *(uint2*)&s[lr * GLDT + lc] = make_uint2(r0.x, r0.y);
    *(uint2*)&s[lr * GLDT + lc + 4] = make_uint2(r0.z, r0.w);
    *(uint2*)&s[(lr + 64) * GLDT + lc] = make_uint2(r1.x, r1.y);
    *(uint2*)&s[(lr + 64) * GLDT + lc + 4] = make_uint2(r1.z, r1.w);
}

template <int NCOLS, bool RESID>
__global__ __launch_bounds__(256) void gemm_bf16(const __nv_bfloat16* __restrict__ A,
                                                 const __nv_bfloat16* __restrict__ Bw,
                                                 __nv_bfloat16* __restrict__ Cb,
                                                 const float* __restrict__ resid,
                                                 float* __restrict__ Cf,
                                                 int K) {
    __shared__ __nv_bfloat16 As[2][GBM * GLDT];
    __shared__ __nv_bfloat16 Bs[2][GBN * GLDT];
    const int tid = threadIdx.x;
    const int warp = tid >> 5, lane = tid & 31;
    const int gid = lane >> 2, tig = lane & 3;
    const int wm = (warp >> 2) * 64, wn = (warp & 3) * 32;
    const int bm = blockIdx.y, bn = blockIdx.x;
    const int lr = tid >> 2;
    const int lc = (tid & 3) * 8;
    const __nv_bfloat16* Ag = A + ((size_t)(bm * GBM + lr)) * K + lc;
    const __nv_bfloat16* Bg = Bw + ((size_t)(bn * GBN + lr)) * K + lc;
    const size_t rstride = (size_t)64 * K;

    float acc[4][4][4];
#pragma unroll
    for (int i = 0; i < 4; i++)
#pragma unroll
        for (int j = 0; j < 4; j++)
#pragma unroll
            for (int r = 0; r < 4; r++) acc[i][j][r] = 0.f;

    uint4 ra0 = *(const uint4*)Ag;
    uint4 ra1 = *(const uint4*)(Ag + rstride);
    uint4 rb0 = *(const uint4*)Bg;
    uint4 rb1 = *(const uint4*)(Bg + rstride);
    st_tile(As[0], lr, lc, ra0, ra1);
    st_tile(Bs[0], lr, lc, rb0, rb1);
    __syncthreads();

    const int KT = K / GBK;
    for (int kt = 0; kt < KT; kt++) {
        int cur = kt & 1;
        if (kt + 1 < KT) {
            const __nv_bfloat16* ap = Ag + (kt + 1) * GBK;
            const __nv_bfloat16* bp = Bg + (kt + 1) * GBK;
            ra0 = *(const uint4*)ap;
            ra1 = *(const uint4*)(ap + rstride);
            rb0 = *(const uint4*)bp;
            rb1 = *(const uint4*)(bp + rstride);
        }
#pragma unroll
        for (int ks = 0; ks < 2; ks++) {
            uint32_t af[4][4], bfr[4][2];
#pragma unroll
            for (int mi = 0; mi < 4; mi++) {
                const __nv_bfloat16* p = &As[cur][(wm + mi * 16 + gid) * GLDT + ks * 16 + tig * 2];
                af[mi][0] = *(const uint32_t*)p;
                af[mi][1] = *(const uint32_t*)(p + 8 * GLDT);
                af[mi][2] = *(const uint32_t*)(p + 8);
                af[mi][3] = *(const uint32_t*)(p + 8 * GLDT + 8);
            }
#pragma unroll
            for (int ni = 0; ni < 4; ni++) {
                const __nv_bfloat16* p = &Bs[cur][(wn + ni * 8 + gid) * GLDT + ks * 16 + tig * 2];
                bfr[ni][0] = *(const uint32_t*)p;
                bfr[ni][1] = *(const uint32_t*)(p + 8);
            }
#pragma unroll
            for (int mi = 0; mi < 4; mi++)
#pragma unroll
                for (int ni = 0; ni < 4; ni++) mma16816(acc[mi][ni], af[mi], bfr[ni]);
        }
        if (kt + 1 < KT) {
            st_tile(As[cur ^ 1], lr, lc, ra0, ra1);
            st_tile(Bs[cur ^ 1], lr, lc, rb0, rb1);
        }
        __syncthreads();
    }

#pragma unroll
    for (int mi = 0; mi < 4; mi++) {
        int r0 = bm * GBM + wm + mi * 16 + gid;
#pragma unroll
        for (int ni = 0; ni < 4; ni++) {
            int col = bn * GBN + wn + ni * 8 + tig * 2;
            size_t i0 = (size_t)r0 * NCOLS + col;
            size_t i1 = (size_t)(r0 + 8) * NCOLS + col;
            if (!RESID) {
                *(__nv_bfloat162*)&Cb[i0] = __floats2bfloat162_rn(acc[mi][ni][0], acc[mi][ni][1]);
                *(__nv_bfloat162*)&Cb[i1] = __floats2bfloat162_rn(acc[mi][ni][2], acc[mi][ni][3]);
            } else {
                float2 v0 = make_float2(acc[mi][ni][0] + resid[i0], acc[mi][ni][1] + resid[i0 + 1]);
                float2 v1 = make_float2(acc[mi][ni][2] + resid[i1], acc[mi][ni][3] + resid[i1 + 1]);
                *(float2*)&Cf[i0] = v0;
                *(float2*)&Cf[i1] = v1;
            }
        }
    }
}

// ---------------- GeGLU ----------------
__global__ __launch_bounds__(256) void geglu_kernel(const __nv_bfloat16* __restrict__ proj,
                                                    __nv_bfloat16* __restrict__ concat,
                                                    __nv_bfloat16* __restrict__ vbuf) {
    int i = blockIdx.x * blockDim.x + threadIdx.x;  // over NROWS * (EXPD/2)
    int row = i >> 10;
    int col = (i & 1023) * 2;
    const size_t pb = (size_t)row * EOUT;
    __nv_bfloat162 l2 = *(const __nv_bfloat162*)&proj[pb + 2 * QKD + col];
    __nv_bfloat162 p2 = *(const __nv_bfloat162*)&proj[pb + 2 * QKD + EXPD + col];
    float p0 = __bfloat162float(p2.x), p1 = __bfloat162float(p2.y);
    float g0 = __bfloat162float(l2.x) * 0.5f * p0 * (1.f + erff(p0 * 0.70710678118654752f));
    float g1 = __bfloat162float(l2.y) * 0.5f * p1 * (1.f + erff(p1 * 0.70710678118654752f));
    __nv_bfloat162 o = __floats2bfloat162_rn(g0, g1);
    if (col < 1024)
        *(__nv_bfloat162*)&concat[(size_t)row * EXPD + col] = o;
    else
        *(__nv_bfloat162*)&vbuf[(size_t)row * DD + col - 1024] = o;
}

// ---------------- flash attention (mma, online softmax) ----------------
// grid (8 q-chunks, B*H); block 256 (8 warps x 16 q rows)
__global__ __launch_bounds__(256, 1) void attn_kernel(const __nv_bfloat16* __restrict__ proj,
                                                      const __nv_bfloat16* __restrict__ vbuf,
                                                      __nv_bfloat16* __restrict__ concat,
                                                      const float* __restrict__ pbm_p,
                                                      const int* __restrict__ fi_p,
                                                      const int* __restrict__ li_p) {
    __shared__ __nv_bfloat16 Ks[128][20];
    __shared__ __nv_bfloat16 Vt[128][136];
    const int tid = threadIdx.x, warp = tid >> 5, lane = tid & 31;
    const int gid = lane >> 2, tig = lane & 3;
    const int bh = blockIdx.y, b = bh >> 3, h = bh & 7;
    const int qbase = blockIdx.x * 128;
    float pbm = *pbm_p;
    const float sp = fmaxf(pbm, 0.f) + log1pf(expf(-fabsf(pbm)));
    int fi = *fi_p; if (fi >= SS) fi = 0;
    int li = *li_p; if (li >= SS) li = 0;

    const int i0 = qbase + warp * 16 + gid;
    const int i1 = i0 + 8;
    uint32_t qa[4];
    {
        const size_t base = ((size_t)(b * SS + i0)) * EOUT + h * 16 + tig * 2;
        qa[0] = *(const uint32_t*)&proj[base];
        qa[1] = *(const uint32_t*)&proj[base + (size_t)8 * EOUT];
        qa[2] = *(const uint32_t*)&proj[base + 8];
        qa[3] = *(const uint32_t*)&proj[base + (size_t)8 * EOUT + 8];
    }
    float m0 = -1e30f, m1 = -1e30f, l0 = 0.f, l1 = 0.f;
    float o[16][4];
#pragma unroll
    for (int ni = 0; ni < 16; ni++)
#pragma unroll
        for (int r = 0; r < 4; r++) o[ni][r] = 0.f;

    const float scale = 0.25f;  // 1/sqrt(16)
    const int qmax = qbase + 127;

    for (int kc = 0; kc < SS / 128; kc++) {
        const int kmin = kc * 128;
        if (kmin > qmax && !((qmax >= fi) && (kmin + 127 >= li))) continue;  // uniform per block

        {  // K chunk -> smem [key][16]
            int r = tid >> 1, c = (tid & 1) * 8;
            const uint4 kv = *(const uint4*)&proj[((size_t)(b * SS + kmin + r)) * EOUT + QKD + h * 16 + c];
            *(uint2*)&Ks[r][c] = make_uint2(kv.x, kv.y);
            *(uint2*)&Ks[r][c + 4] = make_uint2(kv.z, kv.w);
        }
        {  // V chunk transposed -> smem [dv][key]
            int d2 = (tid & 63) * 2, r0 = tid >> 6;
            const size_t gb = ((size_t)(b * SS + kmin)) * DD + h * 128 + d2;
#pragma unroll
            for (int j = 0; j < 32; j++) {
                int r = r0 + j * 4;
                __nv_bfloat162 vv = *(const __nv_bfloat162*)&vbuf[gb + (size_t)r * DD];
                Vt[d2][r] = vv.x;
                Vt[d2 + 1][r] = vv.y;
            }
        }
        __syncthreads();

        float sc[16][4];
#pragma unroll
        for (int ni = 0; ni < 16; ni++) {
            sc[ni][0] = sc[ni][1] = sc[ni][2] = sc[ni][3] = 0.f;
            uint32_t bfr[2];
            bfr[0] = *(const uint32_t*)&Ks[ni * 8 + gid][tig * 2];
            bfr[1] = *(const uint32_t*)&Ks[ni * 8 + gid][tig * 2 + 8];
            mma16816(sc[ni], qa, bfr);
        }
        float rmax0 = -1e30f, rmax1 = -1e30f;
#pragma unroll
        for (int ni = 0; ni < 16; ni++) {
            int jc = kmin + ni * 8 + tig * 2;
#pragma unroll
            for (int r = 0; r < 4; r++) {
                int j = jc + (r & 1);
                int i = (r < 2) ? i0 : i1;
                bool ok = (j <= i) || ((i >= fi) && (j >= li));
                float s = ok ? fmaf(sc[ni][r], scale, sp * (float)(j - i)) : -1e30f;
                sc[ni][r] = s;
                if (r < 2) rmax0 = fmaxf(rmax0, s);
                else rmax1 = fmaxf(rmax1, s);
            }
        }
        rmax0 = fmaxf(rmax0, __shfl_xor_sync(0xffffffffu, rmax0, 1));
        rmax0 = fmaxf(rmax0, __shfl_xor_sync(0xffffffffu, rmax0, 2));
        rmax1 = fmaxf(rmax1, __shfl_xor_sync(0xffffffffu, rmax1, 1));
        rmax1 = fmaxf(rmax1, __shfl_xor_sync(0xffffffffu, rmax1, 2));
        float mn0 = fmaxf(m0, rmax0), mn1 = fmaxf(m1, rmax1);
        float cor0 = __expf(m0 - mn0), cor1 = __expf(m1 - mn1);
        m0 = mn0; m1 = mn1;
        float rs0 = 0.f, rs1 = 0.f;
#pragma unroll
        for (int ni = 0; ni < 16; ni++) {
            sc[ni][0] = __expf(sc[ni][0] - m0); rs0 += sc[ni][0];
            sc[ni][1] = __expf(sc[ni][1] - m0); rs0 += sc[ni][1];
            sc[ni][2] = __expf(sc[ni][2] - m1); rs1 += sc[ni][2];
            sc[ni][3] = __expf(sc[ni][3] - m1); rs1 += sc[ni][3];
        }
        rs0 += __shfl_xor_sync(0xffffffffu, rs0, 1);
        rs0 += __shfl_xor_sync(0xffffffffu, rs0, 2);
        rs1 += __shfl_xor_sync(0xffffffffu, rs1, 1);
        rs1 += __shfl_xor_sync(0xffffffffu, rs1, 2);
        l0 = l0 * cor0 + rs0;
        l1 = l1 * cor1 + rs1;
#pragma unroll
        for (int ni = 0; ni < 16; ni++) {
            o[ni][0] *= cor0; o[ni][1] *= cor0; o[ni][2] *= cor1; o[ni][3] *= cor1;
        }
#pragma unroll
        for (int ks = 0; ks < 8; ks++) {
            uint32_t pa[4];
            pa[0] = packbf(sc[2 * ks][0], sc[2 * ks][1]);
            pa[1] = packbf(sc[2 * ks][2], sc[2 * ks][3]);
            pa[2] = packbf(sc[2 * ks + 1][0], sc[2 * ks + 1][1]);
            pa[3] = packbf(sc[2 * ks + 1][2], sc[2 * ks + 1][3]);
#pragma unroll
            for (int ni = 0; ni < 16; ni++) {
                uint32_t vb[2];
                const __nv_bfloat16* p = &Vt[ni * 8 + gid][ks * 16 + tig * 2];
                vb[0] = *(const uint32_t*)p;
                vb[1] = *(const uint32_t*)(p + 8);
                mma16816(o[ni], pa, vb);
            }
        }
        __syncthreads();
    }

    float inv0 = 1.f / l0, inv1 = 1.f / l1;
#pragma unroll
    for (int ni = 0; ni < 16; ni++) {
        int col = 1024 + h * 128 + ni * 8 + tig * 2;
        *(__nv_bfloat162*)&concat[((size_t)(b * SS) + i0) * EXPD + col] =
            __floats2bfloat162_rn(o[ni][0] * inv0, o[ni][1] * inv0);
        *(__nv_bfloat162*)&concat[((size_t)(b * SS) + i1) * EXPD + col] =
            __floats2bfloat162_rn(o[ni][2] * inv1, o[ni][3] * inv1);
    }
}

// ---------------- launch ----------------
extern "C" void kernel_launch(void* const* d_in, const int* in_sizes, int n_in,
                              void* d_out, int out_size) {
    const float* x = (const float*)d_in[0];
    const float* norm_w = (const float*)d_in[1];
    const float* expand_w = (const float*)d_in[2];
    const float* project_w = (const float*)d_in[3];
    const float* pbm = (const float*)d_in[4];
    const int* fi = (const int*)d_in[5];
    const int* li = (const int*)d_in[6];
    float* out = (float*)d_out;

    void *p_xn, *p_proj, *p_concat, *p_v, *p_wexp, *p_wproj;
    cudaGetSymbolAddress(&p_xn, g_xn);
    cudaGetSymbolAddress(&p_proj, g_proj);
    cudaGetSymbolAddress(&p_concat, g_concat);
    cudaGetSymbolAddress(&p_v, g_v);
    cudaGetSymbolAddress(&p_wexp, g_wexp);
    cudaGetSymbolAddress(&p_wproj, g_wproj);
    __nv_bfloat16* xn = (__nv_bfloat16*)p_xn;
    __nv_bfloat16* proj = (__nv_bfloat16*)p_proj;
    __nv_bfloat16* concat = (__nv_bfloat16*)p_concat;
    __nv_bfloat16* vb = (__nv_bfloat16*)p_v;
    __nv_bfloat16* wexp = (__nv_bfloat16*)p_wexp;
    __nv_bfloat16* wproj = (__nv_bfloat16*)p_wproj;

    // weights -> bf16
    cvt_kernel<<<(EOUT * DD / 4 + 255) / 256, 256>>>(expand_w, wexp, EOUT * DD / 4);
    cvt_kernel<<<(DD * EXPD / 4 + 255) / 256, 256>>>(project_w, wproj, DD * EXPD / 4);

    // layernorm
    ln_kernel<<<NROWS, 256>>>(x, norm_w, xn);

    // expand GEMM: proj[16384,4352] = xn[16384,1024] @ wexp[4352,1024]^T
    gemm_bf16<EOUT, false><<<dim3(EOUT / GBN, NROWS / GBM), 256>>>(xn, wexp, proj, nullptr, nullptr, DD);

    // geglu -> concat[:, :1024] and v buffer
    geglu_kernel<<<NROWS * (EXPD / 2) / 256, 256>>>(proj, concat, vb);

    // attention -> concat[:, 1024:2048]
    attn_kernel<<<dim3(SS / 128, BB * HH), 256>>>(proj, vb, concat, pbm, fi, li);

    // project GEMM + residual: out[16384,1024] = concat[16384,2048] @ wproj[1024,2048]^T + x
    gemm_bf16<DD, true><<<dim3(DD / GBN, NROWS / GBM), 256>>>(concat, wproj, nullptr, x, out, EXPD);
}

// round 5
// speedup vs baseline: 1.3865x; 1.3782x over previous
#include <cuda_runtime.h>
#include <cuda_bf16.h>
#include <cstdint>
#include <math.h>

// ---------------- problem constants ----------------
#define BB 16
#define SS 1024
#define DD 1024
#define HH 8
#define QKD 128          // q/k width
#define EXPD 2048
#define NROWS (BB*SS)    // 16384
#define EOUT (2*QKD + 2*EXPD)  // 4352

// ---------------- scratch (static device, no allocation) ----------------
__device__ __nv_bfloat16 g_xn[(size_t)NROWS * DD];
__device__ __nv_bfloat16 g_proj[(size_t)NROWS * EOUT];
__device__ __nv_bfloat16 g_concat[(size_t)NROWS * EXPD];   // [0,1024): geglu_local, [1024,2048): attention
__device__ __nv_bfloat16 g_v[(size_t)NROWS * DD];
__device__ __nv_bfloat16 g_wexp[(size_t)EOUT * DD];
__device__ __nv_bfloat16 g_wproj[(size_t)DD * EXPD];

// ---------------- helpers ----------------
__device__ __forceinline__ void mma16816(float d[4], const uint32_t a[4], const uint32_t b[2]) {
    asm volatile(
        "mma.sync.aligned.m16n8k16.row.col.f32.bf16.bf16.f32 "
        "{%0,%1,%2,%3},{%4,%5,%6,%7},{%8,%9},{%0,%1,%2,%3};\n"
        : "+f"(d[0]), "+f"(d[1]), "+f"(d[2]), "+f"(d[3])
        : "r"(a[0]), "r"(a[1]), "r"(a[2]), "r"(a[3]), "r"(b[0]), "r"(b[1]));
}

__device__ __forceinline__ uint32_t packbf(float a, float b) {
    __nv_bfloat162 t = __floats2bfloat162_rn(a, b);
    return *reinterpret_cast<uint32_t*>(&t);
}

__device__ __forceinline__ void ldsm4(uint32_t r[4], uint32_t saddr) {
    asm volatile("ldmatrix.sync.aligned.m8n8.x4.shared.b16 {%0,%1,%2,%3}, [%4];"
                 : "=r"(r[0]), "=r"(r[1]), "=r"(r[2]), "=r"(r[3]) : "r"(saddr));
}

__device__ __forceinline__ void cp16(uint32_t saddr, const void* g) {
    asm volatile("cp.async.cg.shared.global [%0], [%1], 16;" :: "r"(saddr), "l"(g));
}

// ---------------- fp32 -> bf16 weight convert ----------------
__global__ void cvt_kernel(const float* __restrict__ src, __nv_bfloat16* __restrict__ dst, int n4) {
    int i = blockIdx.x * blockDim.x + threadIdx.x;
    if (i < n4) {
        float4 v = ((const float4*)src)[i];
        __nv_bfloat162* d = (__nv_bfloat162*)(dst + (size_t)i * 4);
        d[0] = __floats2bfloat162_rn(v.x, v.y);
        d[1] = __floats2bfloat162_rn(v.z, v.w);
    }
}

// ---------------- LayerNorm: one block (256 thr) per row ----------------
__global__ __launch_bounds__(256) void ln_kernel(const float* __restrict__ x,
                                                 const float* __restrict__ w,
                                                 __nv_bfloat16* __restrict__ out) {
    int row = blockIdx.x;
    float4 v = ((const float4*)(x + (size_t)row * DD))[threadIdx.x];
    float s = v.x + v.y + v.z + v.w;
    float s2 = v.x * v.x + v.y * v.y + v.z * v.z + v.w * v.w;
#pragma unroll
    for (int o = 16; o; o >>= 1) {
        s += __shfl_xor_sync(0xffffffffu, s, o);
        s2 += __shfl_xor_sync(0xffffffffu, s2, o);
    }
    __shared__ float rs[8], rs2[8];
    int warp = threadIdx.x >> 5, lane = threadIdx.x & 31;
    if (!lane) { rs[warp] = s; rs2[warp] = s2; }
    __syncthreads();
    if (threadIdx.x == 0) {
        float a = 0.f, b = 0.f;
#pragma unroll
        for (int i = 0; i < 8; i++) { a += rs[i]; b += rs2[i]; }
        rs[0] = a; rs2[0] = b;
    }
    __syncthreads();
    float mu = rs[0] * (1.f / DD);
    float var = rs2[0] * (1.f / DD) - mu * mu;
    float r = rsqrtf(var + 1e-5f);
    float4 w4 = ((const float4*)w)[threadIdx.x];
    __nv_bfloat16* op = out + (size_t)row * DD + threadIdx.x * 4;
    *(__nv_bfloat162*)op = __floats2bfloat162_rn((v.x - mu) * r * w4.x, (v.y - mu) * r * w4.y);
    *(__nv_bfloat162*)(op + 2) = __floats2bfloat162_rn((v.z - mu) * r * w4.z, (v.w - mu) * r * w4.w);
}

// ---------------- bf16 GEMM: C[M,N] = A[M,K] * Bw[N,K]^T ----------------
// BM=128, BN=128, BK=64, 256 threads, warps 2x4, warp tile 64x32 (4x4 m16n8k16)
// 3-stage cp.async pipeline, ldmatrix.x4 fragment loads, XOR-swizzled smem.
// Smem per stage: A 128x64 bf16 = 16KB, B 16KB. Total dyn smem = 3*32KB = 96KB.
#define GSTG 3
#define GSTAGE_BYTES (128 * 64 * 2)
#define GSMEM_BYTES (2 * GSTG * GSTAGE_BYTES)

template <int NCOLS, bool RESID>
__global__ __launch_bounds__(256, 2) void gemm_bf16(const __nv_bfloat16* __restrict__ A,
                                                    const __nv_bfloat16* __restrict__ Bw,
                                                    __nv_bfloat16* __restrict__ Cb,
                                                    const float* __restrict__ resid,
                                                    float* __restrict__ Cf,
                                                    int K) {
    extern __shared__ __nv_bfloat16 smbuf[];
    const int tid = threadIdx.x;
    const int warp = tid >> 5, lane = tid & 31;
    const int gid = lane >> 2, tig = lane & 3;
    const int wm = (warp >> 2) * 64, wn = (warp & 3) * 32;
    const int bm = blockIdx.y, bn = blockIdx.x;

    const uint32_t sbase = (uint32_t)__cvta_generic_to_shared(smbuf);

    // global->smem mapping: each thread copies 4 A-chunks + 4 B-chunks of 16B
    const int r = tid >> 3, c = tid & 7;            // r in [0,32), c = 16B chunk
    const int swz = (c ^ (r & 7)) * 16;             // byte offset of swizzled chunk
    const __nv_bfloat16* Ag = A + ((size_t)(bm * 128 + r)) * K + c * 8;
    const __nv_bfloat16* Bg = Bw + ((size_t)(bn * 128 + r)) * K + c * 8;

    auto load_stage = [&](int s, int kt) {
        uint32_t sa = sbase + s * GSTAGE_BYTES + r * 128 + swz;
        uint32_t sb = sbase + GSTG * GSTAGE_BYTES + s * GSTAGE_BYTES + r * 128 + swz;
        const __nv_bfloat16* ag = Ag + kt * 64;
        const __nv_bfloat16* bg = Bg + kt * 64;
#pragma unroll
        for (int it = 0; it < 4; it++) {
            cp16(sa + it * 32 * 128, ag + (size_t)(it * 32) * K);
            cp16(sb + it * 32 * 128, bg + (size_t)(it * 32) * K);
        }
    };

    float acc[4][4][4];
#pragma unroll
    for (int i = 0; i < 4; i++)
#pragma unroll
        for (int j = 0; j < 4; j++)
#pragma unroll
            for (int q = 0; q < 4; q++) acc[i][j][q] = 0.f;

    load_stage(0, 0);
    asm volatile("cp.async.commit_group;" ::: "memory");
    load_stage(1, 1);
    asm volatile("cp.async.commit_group;" ::: "memory");

    // ldmatrix per-lane row indices (constant across kt/ks)
    const int a_lrow = lane & 15;                    // row within 16-row A tile
    const int a_chi = lane >> 4;                     // 0/1 -> k-chunk parity
    const int b_lrow = (lane & 7) + ((lane >> 4) << 3);
    const int b_chi = (lane >> 3) & 1;

    const int KT = K >> 6;
    for (int kt = 0; kt < KT; kt++) {
        asm volatile("cp.async.wait_group 1;" ::: "memory");
        __syncthreads();
        if (kt + 2 < KT) load_stage((kt + 2) % GSTG, kt + 2);
        asm volatile("cp.async.commit_group;" ::: "memory");

        const uint32_t sA = sbase + (kt % GSTG) * GSTAGE_BYTES;
        const uint32_t sB = sA + GSTG * GSTAGE_BYTES;
#pragma unroll
        for (int ks = 0; ks < 4; ks++) {
            uint32_t af[4][4], bfr[4][2];
#pragma unroll
            for (int mi = 0; mi < 4; mi++) {
                int row = wm + mi * 16 + a_lrow;
                int cc = ks * 2 + a_chi;
                ldsm4(af[mi], sA + row * 128 + ((cc ^ (row & 7)) * 16));
            }
#pragma unroll
            for (int j = 0; j < 2; j++) {
                int row = wn + j * 16 + b_lrow;
                int cc = ks * 2 + b_chi;
                uint32_t rr[4];
                ldsm4(rr, sB + row * 128 + ((cc ^ (row & 7)) * 16));
                bfr[j * 2][0] = rr[0]; bfr[j * 2][1] = rr[1];
                bfr[j * 2 + 1][0] = rr[2]; bfr[j * 2 + 1][1] = rr[3];
            }
#pragma unroll
            for (int mi = 0; mi < 4; mi++)
#pragma unroll
                for (int ni = 0; ni < 4; ni++) mma16816(acc[mi][ni], af[mi], bfr[ni]);
        }
        __syncthreads();
    }

#pragma unroll
    for (int mi = 0; mi < 4; mi++) {
        int r0 = bm * 128 + wm + mi * 16 + gid;
#pragma unroll
        for (int ni = 0; ni < 4; ni++) {
            int col = bn * 128 + wn + ni * 8 + tig * 2;
            size_t i0 = (size_t)r0 * NCOLS + col;
            size_t i1 = (size_t)(r0 + 8) * NCOLS + col;
            if (!RESID) {
                *(__nv_bfloat162*)&Cb[i0] = __floats2bfloat162_rn(acc[mi][ni][0], acc[mi][ni][1]);
                *(__nv_bfloat162*)&Cb[i1] = __floats2bfloat162_rn(acc[mi][ni][2], acc[mi][ni][3]);
            } else {
                float2 v0 = make_float2(acc[mi][ni][0] + resid[i0], acc[mi][ni][1] + resid[i0 + 1]);
                float2 v1 = make_float2(acc[mi][ni][2] + resid[i1], acc[mi][ni][3] + resid[i1 + 1]);
                *(float2*)&Cf[i0] = v0;
                *(float2*)&Cf[i1] = v1;
            }
        }
    }
}

// ---------------- GeGLU ----------------
__global__ __launch_bounds__(256) void geglu_kernel(const __nv_bfloat16* __restrict__ proj,
                                                    __nv_bfloat16* __restrict__ concat,
                                                    __nv_bfloat16* __restrict__ vbuf) {
    int i = blockIdx.x * blockDim.x + threadIdx.x;  // over NROWS * (EXPD/2)
    int row = i >> 10;
    int col = (i & 1023) * 2;
    const size_t pb = (size_t)row * EOUT;
    __nv_bfloat162 l2 = *(const __nv_bfloat162*)&proj[pb + 2 * QKD + col];
    __nv_bfloat162 p2 = *(const __nv_bfloat162*)&proj[pb + 2 * QKD + EXPD + col];
    float p0 = __bfloat162float(p2.x), p1 = __bfloat162float(p2.y);
    float g0 = __bfloat162float(l2.x) * 0.5f * p0 * (1.f + erff(p0 * 0.70710678118654752f));
    float g1 = __bfloat162float(l2.y) * 0.5f * p1 * (1.f + erff(p1 * 0.70710678118654752f));
    __nv_bfloat162 o = __floats2bfloat162_rn(g0, g1);
    if (col < 1024)
        *(__nv_bfloat162*)&concat[(size_t)row * EXPD + col] = o;
    else
        *(__nv_bfloat162*)&vbuf[(size_t)row * DD + col - 1024] = o;
}

// ---------------- flash attention (mma, online softmax) ----------------
// grid (8 q-chunks, B*H); block 256 (8 warps x 16 q rows)
__global__ __launch_bounds__(256, 1) void attn_kernel(const __nv_bfloat16* __restrict__ proj,
                                                      const __nv_bfloat16* __restrict__ vbuf,
                                                      __nv_bfloat16* __restrict__ concat,
                                                      const float* __restrict__ pbm_p,
                                                      const int* __restrict__ fi_p,
                                                      const int* __restrict__ li_p) {
    __shared__ __nv_bfloat16 Ks[128][20];
    __shared__ __nv_bfloat16 Vt[128][136];
    const int tid = threadIdx.x, warp = tid >> 5, lane = tid & 31;
    const int gid = lane >> 2, tig = lane & 3;
    const int bh = blockIdx.y, b = bh >> 3, h = bh & 7;
    const int qbase = blockIdx.x * 128;
    float pbm = *pbm_p;
    const float sp = fmaxf(pbm, 0.f) + log1pf(expf(-fabsf(pbm)));
    int fi = *fi_p; if (fi >= SS) fi = 0;
    int li = *li_p; if (li >= SS) li = 0;

    const int i0 = qbase + warp * 16 + gid;
    const int i1 = i0 + 8;
    uint32_t qa[4];
    {
        const size_t base = ((size_t)(b * SS + i0)) * EOUT + h * 16 + tig * 2;
        qa[0] = *(const uint32_t*)&proj[base];
        qa[1] = *(const uint32_t*)&proj[base + (size_t)8 * EOUT];
        qa[2] = *(const uint32_t*)&proj[base + 8];
        qa[3] = *(const uint32_t*)&proj[base + (size_t)8 * EOUT + 8];
    }
    float m0 = -1e30f, m1 = -1e30f, l0 = 0.f, l1 = 0.f;
    float o[16][4];
#pragma unroll
    for (int ni = 0; ni < 16; ni++)
#pragma unroll
        for (int r = 0; r < 4; r++) o[ni][r] = 0.f;

    const float scale = 0.25f;  // 1/sqrt(16)
    const int qmax = qbase + 127;

    for (int kc = 0; kc < SS / 128; kc++) {
        const int kmin = kc * 128;
        if (kmin > qmax && !((qmax >= fi) && (kmin + 127 >= li))) continue;  // uniform per block

        {  // K chunk -> smem [key][16]
            int r = tid >> 1, c = (tid & 1) * 8;
            const uint4 kv = *(const uint4*)&proj[((size_t)(b * SS + kmin + r)) * EOUT + QKD + h * 16 + c];
            *(uint2*)&Ks[r][c] = make_uint2(kv.x, kv.y);
            *(uint2*)&Ks[r][c + 4] = make_uint2(kv.z, kv.w);
        }
        {  // V chunk transposed -> smem [dv][key]
            int d2 = (tid & 63) * 2, r0 = tid >> 6;
            const size_t gb = ((size_t)(b * SS + kmin)) * DD + h * 128 + d2;
#pragma unroll
            for (int j = 0; j < 32; j++) {
                int r = r0 + j * 4;
                __nv_bfloat162 vv = *(const __nv_bfloat162*)&vbuf[gb + (size_t)r * DD];
                Vt[d2][r] = vv.x;
                Vt[d2 + 1][r] = vv.y;
            }
        }
        __syncthreads();

        float sc[16][4];
#pragma unroll
        for (int ni = 0; ni < 16; ni++) {
            sc[ni][0] = sc[ni][1] = sc[ni][2] = sc[ni][3] = 0.f;
            uint32_t bfr[2];
            bfr[0] = *(const uint32_t*)&Ks[ni * 8 + gid][tig * 2];
            bfr[1] = *(const uint32_t*)&Ks[ni * 8 + gid][tig * 2 + 8];
            mma16816(sc[ni], qa, bfr);
        }
        float rmax0 = -1e30f, rmax1 = -1e30f;
#pragma unroll
        for (int ni = 0; ni < 16; ni++) {
            int jc = kmin + ni * 8 + tig * 2;
#pragma unroll
            for (int r = 0; r < 4; r++) {
                int j = jc + (r & 1);
                int i = (r < 2) ? i0 : i1;
                bool ok = (j <= i) || ((i >= fi) && (j >= li));
                float s = ok ? fmaf(sc[ni][r], scale, sp * (float)(j - i)) : -1e30f;
                sc[ni][r] = s;
                if (r < 2) rmax0 = fmaxf(rmax0, s);
                else rmax1 = fmaxf(rmax1, s);
            }
        }
        rmax0 = fmaxf(rmax0, __shfl_xor_sync(0xffffffffu, rmax0, 1));
        rmax0 = fmaxf(rmax0, __shfl_xor_sync(0xffffffffu, rmax0, 2));
        rmax1 = fmaxf(rmax1, __shfl_xor_sync(0xffffffffu, rmax1, 1));
        rmax1 = fmaxf(rmax1, __shfl_xor_sync(0xffffffffu, rmax1, 2));
        float mn0 = fmaxf(m0, rmax0), mn1 = fmaxf(m1, rmax1);
        float cor0 = __expf(m0 - mn0), cor1 = __expf(m1 - mn1);
        m0 = mn0; m1 = mn1;
        float rs0 = 0.f, rs1 = 0.f;
#pragma unroll
        for (int ni = 0; ni < 16; ni++) {
            sc[ni][0] = __expf(sc[ni][0] - m0); rs0 += sc[ni][0];
            sc[ni][1] = __expf(sc[ni][1] - m0); rs0 += sc[ni][1];
            sc[ni][2] = __expf(sc[ni][2] - m1); rs1 += sc[ni][2];
            sc[ni][3] = __expf(sc[ni][3] - m1); rs1 += sc[ni][3];
        }
        rs0 += __shfl_xor_sync(0xffffffffu, rs0, 1);
        rs0 += __shfl_xor_sync(0xffffffffu, rs0, 2);
        rs1 += __shfl_xor_sync(0xffffffffu, rs1, 1);
        rs1 += __shfl_xor_sync(0xffffffffu, rs1, 2);
        l0 = l0 * cor0 + rs0;
        l1 = l1 * cor1 + rs1;
#pragma unroll
        for (int ni = 0; ni < 16; ni++) {
            o[ni][0] *= cor0; o[ni][1] *= cor0; o[ni][2] *= cor1; o[ni][3] *= cor1;
        }
#pragma unroll
        for (int ks = 0; ks < 8; ks++) {
            uint32_t pa[4];
            pa[0] = packbf(sc[2 * ks][0], sc[2 * ks][1]);
            pa[1] = packbf(sc[2 * ks][2], sc[2 * ks][3]);
            pa[2] = packbf(sc[2 * ks + 1][0], sc[2 * ks + 1][1]);
            pa[3] = packbf(sc[2 * ks + 1][2], sc[2 * ks + 1][3]);
#pragma unroll
            for (int ni = 0; ni < 16; ni++) {
                uint32_t vb[2];
                const __nv_bfloat16* p = &Vt[ni * 8 + gid][ks * 16 + tig * 2];
                vb[0] = *(const uint32_t*)p;
                vb[1] = *(const uint32_t*)(p + 8);
                mma16816(o[ni], pa, vb);
            }
        }
        __syncthreads();
    }

    float inv0 = 1.f / l0, inv1 = 1.f / l1;
#pragma unroll
    for (int ni = 0; ni < 16; ni++) {
        int col = 1024 + h * 128 + ni * 8 + tig * 2;
        *(__nv_bfloat162*)&concat[((size_t)(b * SS) + i0) * EXPD + col] =
            __floats2bfloat162_rn(o[ni][0] * inv0, o[ni][1] * inv0);
        *(__nv_bfloat162*)&concat[((size_t)(b * SS) + i1) * EXPD + col] =
            __floats2bfloat162_rn(o[ni][2] * inv1, o[ni][3] * inv1);
    }
}

// ---------------- launch ----------------
extern "C" void kernel_launch(void* const* d_in, const int* in_sizes, int n_in,
                              void* d_out, int out_size) {
    const float* x = (const float*)d_in[0];
    const float* norm_w = (const float*)d_in[1];
    const float* expand_w = (const float*)d_in[2];
    const float* project_w = (const float*)d_in[3];
    const float* pbm = (const float*)d_in[4];
    const int* fi = (const int*)d_in[5];
    const int* li = (const int*)d_in[6];
    float* out = (float*)d_out;

    void *p_xn, *p_proj, *p_concat, *p_v, *p_wexp, *p_wproj;
    cudaGetSymbolAddress(&p_xn, g_xn);
    cudaGetSymbolAddress(&p_proj, g_proj);
    cudaGetSymbolAddress(&p_concat, g_concat);
    cudaGetSymbolAddress(&p_v, g_v);
    cudaGetSymbolAddress(&p_wexp, g_wexp);
    cudaGetSymbolAddress(&p_wproj, g_wproj);
    __nv_bfloat16* xn = (__nv_bfloat16*)p_xn;
    __nv_bfloat16* proj = (__nv_bfloat16*)p_proj;
    __nv_bfloat16* concat = (__nv_bfloat16*)p_concat;
    __nv_bfloat16* vb = (__nv_bfloat16*)p_v;
    __nv_bfloat16* wexp = (__nv_bfloat16*)p_wexp;
    __nv_bfloat16* wproj = (__nv_bfloat16*)p_wproj;

    // opt-in to 96KB dynamic smem for the pipelined GEMM (host-side, capture-safe)
    cudaFuncSetAttribute(gemm_bf16<EOUT, false>, cudaFuncAttributeMaxDynamicSharedMemorySize, GSMEM_BYTES);
    cudaFuncSetAttribute(gemm_bf16<DD, true>, cudaFuncAttributeMaxDynamicSharedMemorySize, GSMEM_BYTES);

    // weights -> bf16
    cvt_kernel<<<(EOUT * DD / 4 + 255) / 256, 256>>>(expand_w, wexp, EOUT * DD / 4);
    cvt_kernel<<<(DD * EXPD / 4 + 255) / 256, 256>>>(project_w, wproj, DD * EXPD / 4);

    // layernorm
    ln_kernel<<<NROWS, 256>>>(x, norm_w, xn);

    // expand GEMM: proj[16384,4352] = xn[16384,1024] @ wexp[4352,1024]^T
    gemm_bf16<EOUT, false><<<dim3(EOUT / 128, NROWS / 128), 256, GSMEM_BYTES>>>(xn, wexp, proj, nullptr, nullptr, DD);

    // geglu -> concat[:, :1024] and v buffer
    geglu_kernel<<<NROWS * (EXPD / 2) / 256, 256>>>(proj, concat, vb);

    // attention -> concat[:, 1024:2048]
    attn_kernel<<<dim3(SS / 128, BB * HH), 256>>>(proj, vb, concat, pbm, fi, li);

    // project GEMM + residual: out[16384,1024] = concat[16384,2048] @ wproj[1024,2048]^T + x
    gemm_bf16<DD, true><<<dim3(DD / 128, NROWS / 128), 256, GSMEM_BYTES>>>(concat, wproj, nullptr, x, out, EXPD);
}

// round 7
// speedup vs baseline: 1.4999x; 1.0818x over previous
#include <cuda_runtime.h>
#include <cuda_bf16.h>
#include <cstdint>
#include <math.h>

// ---------------- problem constants ----------------
#define BB 16
#define SS 1024
#define DD 1024
#define HH 8
#define QKD 128          // q/k width
#define EXPD 2048
#define NROWS (BB*SS)    // 16384
#define EOUT (2*QKD + 2*EXPD)  // 4352

// ---------------- scratch (static device, no allocation) ----------------
__device__ __nv_bfloat16 g_xn[(size_t)NROWS * DD];
__device__ __nv_bfloat16 g_qk[(size_t)NROWS * 256];       // [q(128) | k(128)]
__device__ __nv_bfloat16 g_concat[(size_t)NROWS * EXPD];  // [0,1024): geglu_local, [1024,2048): attention
__device__ __nv_bfloat16 g_v[(size_t)NROWS * DD];
__device__ __nv_bfloat16 g_wexp[(size_t)EOUT * DD];       // reordered: [q,k | interleaved lin/pre]
__device__ __nv_bfloat16 g_wproj[(size_t)DD * EXPD];

// ---------------- helpers ----------------
__device__ __forceinline__ void mma16816(float d[4], const uint32_t a[4], const uint32_t b[2]) {
    asm volatile(
        "mma.sync.aligned.m16n8k16.row.col.f32.bf16.bf16.f32 "
        "{%0,%1,%2,%3},{%4,%5,%6,%7},{%8,%9},{%0,%1,%2,%3};\n"
        : "+f"(d[0]), "+f"(d[1]), "+f"(d[2]), "+f"(d[3])
        : "r"(a[0]), "r"(a[1]), "r"(a[2]), "r"(a[3]), "r"(b[0]), "r"(b[1]));
}

__device__ __forceinline__ uint32_t packbf(float a, float b) {
    __nv_bfloat162 t = __floats2bfloat162_rn(a, b);
    return *reinterpret_cast<uint32_t*>(&t);
}

__device__ __forceinline__ void ldsm4(uint32_t r[4], uint32_t saddr) {
    asm volatile("ldmatrix.sync.aligned.m8n8.x4.shared.b16 {%0,%1,%2,%3}, [%4];"
                 : "=r"(r[0]), "=r"(r[1]), "=r"(r[2]), "=r"(r[3]) : "r"(saddr));
}

__device__ __forceinline__ void cp16(uint32_t saddr, const void* g) {
    asm volatile("cp.async.cg.shared.global [%0], [%1], 16;" :: "r"(saddr), "l"(g));
}

__device__ __forceinline__ float gelu_exact(float p) {
    return 0.5f * p * (1.f + erff(p * 0.70710678118654752f));
}

// ---------------- weight converts ----------------
__global__ void cvt_kernel(const float* __restrict__ src, __nv_bfloat16* __restrict__ dst, int n4) {
    int i = blockIdx.x * blockDim.x + threadIdx.x;
    if (i < n4) {
        float4 v = ((const float4*)src)[i];
        __nv_bfloat162* d = (__nv_bfloat162*)(dst + (size_t)i * 4);
        d[0] = __floats2bfloat162_rn(v.x, v.y);
        d[1] = __floats2bfloat162_rn(v.z, v.w);
    }
}

// expand_w convert + row reorder: dst row r<256 -> src r; else t=r-256,
// even t -> lin row 256+t/2, odd t -> pre row 2304+t/2.
__global__ void cvt_exp_kernel(const float* __restrict__ src, __nv_bfloat16* __restrict__ dst) {
    int i = blockIdx.x * blockDim.x + threadIdx.x;   // over EOUT * (DD/4)
    int r = i >> 8;                                   // dst row
    int c4 = i & 255;                                 // 4-float chunk within row
    int t = r - 256;
    int sr = (r < 256) ? r : ((t & 1) ? (2304 + (t >> 1)) : (256 + (t >> 1)));
    float4 v = ((const float4*)(src + (size_t)sr * DD))[c4];
    __nv_bfloat162* d = (__nv_bfloat162*)(dst + (size_t)r * DD + c4 * 4);
    d[0] = __floats2bfloat162_rn(v.x, v.y);
    d[1] = __floats2bfloat162_rn(v.z, v.w);
}

// ---------------- LayerNorm ----------------
__global__ __launch_bounds__(256) void ln_kernel(const float* __restrict__ x,
                                                 const float* __restrict__ w,
                                                 __nv_bfloat16* __restrict__ out) {
    int row = blockIdx.x;
    float4 v = ((const float4*)(x + (size_t)row * DD))[threadIdx.x];
    float s = v.x + v.y + v.z + v.w;
    float s2 = v.x * v.x + v.y * v.y + v.z * v.z + v.w * v.w;
#pragma unroll
    for (int o = 16; o; o >>= 1) {
        s += __shfl_xor_sync(0xffffffffu, s, o);
        s2 += __shfl_xor_sync(0xffffffffu, s2, o);
    }
    __shared__ float rs[8], rs2[8];
    int warp = threadIdx.x >> 5, lane = threadIdx.x & 31;
    if (!lane) { rs[warp] = s; rs2[warp] = s2; }
    __syncthreads();
    if (threadIdx.x == 0) {
        float a = 0.f, b = 0.f;
#pragma unroll
        for (int i = 0; i < 8; i++) { a += rs[i]; b += rs2[i]; }
        rs[0] = a; rs2[0] = b;
    }
    __syncthreads();
    float mu = rs[0] * (1.f / DD);
    float var = rs2[0] * (1.f / DD) - mu * mu;
    float r = rsqrtf(var + 1e-5f);
    float4 w4 = ((const float4*)w)[threadIdx.x];
    __nv_bfloat16* op = out + (size_t)row * DD + threadIdx.x * 4;
    *(__nv_bfloat162*)op = __floats2bfloat162_rn((v.x - mu) * r * w4.x, (v.y - mu) * r * w4.y);
    *(__nv_bfloat162*)(op + 2) = __floats2bfloat162_rn((v.z - mu) * r * w4.z, (v.w - mu) * r * w4.w);
}

// ---------------- bf16 GEMM: C[M,N] = A[M,K] * Bw[N,K]^T ----------------
// BM=128, BN=128, BK=64, 256 threads, warps 2x4, warp tile 64x32 (4x4 m16n8k16)
// 3-stage cp.async pipeline, ldmatrix.x4 fragment loads, XOR-swizzled smem.
// MODE 0: fused GEMM1 epilogue (qk buffer + geglu -> concat/vbuf)
// MODE 1: fp32 out with residual add (GEMM2)
#define GSTG 3
#define GSTAGE_BYTES (128 * 64 * 2)
#define GSMEM_BYTES (2 * GSTG * GSTAGE_BYTES)

template <int MODE>
__global__ __launch_bounds__(256, 2) void gemm_bf16(const __nv_bfloat16* __restrict__ A,
                                                    const __nv_bfloat16* __restrict__ Bw,
                                                    __nv_bfloat16* __restrict__ qk,
                                                    __nv_bfloat16* __restrict__ concat,
                                                    __nv_bfloat16* __restrict__ vbuf,
                                                    const float* __restrict__ resid,
                                                    float* __restrict__ Cf,
                                                    int K) {
    extern __shared__ __nv_bfloat16 smbuf[];
    const int tid = threadIdx.x;
    const int warp = tid >> 5, lane = tid & 31;
    const int gid = lane >> 2, tig = lane & 3;
    const int wm = (warp >> 2) * 64, wn = (warp & 3) * 32;
    const int bm = blockIdx.y, bn = blockIdx.x;

    const uint32_t sbase = (uint32_t)__cvta_generic_to_shared(smbuf);

    const int r = tid >> 3, c = tid & 7;
    const int swz = (c ^ (r & 7)) * 16;
    const __nv_bfloat16* Ag = A + ((size_t)(bm * 128 + r)) * K + c * 8;
    const __nv_bfloat16* Bg = Bw + ((size_t)(bn * 128 + r)) * K + c * 8;

    auto load_stage = [&](int s, int kt) {
        uint32_t sa = sbase + s * GSTAGE_BYTES + r * 128 + swz;
        uint32_t sb = sbase + GSTG * GSTAGE_BYTES + s * GSTAGE_BYTES + r * 128 + swz;
        const __nv_bfloat16* ag = Ag + kt * 64;
        const __nv_bfloat16* bg = Bg + kt * 64;
#pragma unroll
        for (int it = 0; it < 4; it++) {
            cp16(sa + it * 32 * 128, ag + (size_t)(it * 32) * K);
            cp16(sb + it * 32 * 128, bg + (size_t)(it * 32) * K);
        }
    };

    float acc[4][4][4];
#pragma unroll
    for (int i = 0; i < 4; i++)
#pragma unroll
        for (int j = 0; j < 4; j++)
#pragma unroll
            for (int q = 0; q < 4; q++) acc[i][j][q] = 0.f;

    load_stage(0, 0);
    asm volatile("cp.async.commit_group;" ::: "memory");
    load_stage(1, 1);
    asm volatile("cp.async.commit_group;" ::: "memory");

    const int a_lrow = lane & 15;
    const int a_chi = lane >> 4;
    const int b_lrow = (lane & 7) + ((lane >> 4) << 3);
    const int b_chi = (lane >> 3) & 1;

    const int KT = K >> 6;
    for (int kt = 0; kt < KT; kt++) {
        asm volatile("cp.async.wait_group 1;" ::: "memory");
        __syncthreads();
        if (kt + 2 < KT) load_stage((kt + 2) % GSTG, kt + 2);
        asm volatile("cp.async.commit_group;" ::: "memory");

        const uint32_t sA = sbase + (kt % GSTG) * GSTAGE_BYTES;
        const uint32_t sB = sA + GSTG * GSTAGE_BYTES;
#pragma unroll
        for (int ks = 0; ks < 4; ks++) {
            uint32_t af[4][4], bfr[4][2];
#pragma unroll
            for (int mi = 0; mi < 4; mi++) {
                int row = wm + mi * 16 + a_lrow;
                int cc = ks * 2 + a_chi;
                ldsm4(af[mi], sA + row * 128 + ((cc ^ (row & 7)) * 16));
            }
#pragma unroll
            for (int j = 0; j < 2; j++) {
                int row = wn + j * 16 + b_lrow;
                int cc = ks * 2 + b_chi;
                uint32_t rr[4];
                ldsm4(rr, sB + row * 128 + ((cc ^ (row & 7)) * 16));
                bfr[j * 2][0] = rr[0]; bfr[j * 2][1] = rr[1];
                bfr[j * 2 + 1][0] = rr[2]; bfr[j * 2 + 1][1] = rr[3];
            }
#pragma unroll
            for (int mi = 0; mi < 4; mi++)
#pragma unroll
                for (int ni = 0; ni < 4; ni++) mma16816(acc[mi][ni], af[mi], bfr[ni]);
        }
        __syncthreads();
    }

#pragma unroll
    for (int mi = 0; mi < 4; mi++) {
        int r0 = bm * 128 + wm + mi * 16 + gid;
#pragma unroll
        for (int ni = 0; ni < 4; ni++) {
            int col = bn * 128 + wn + ni * 8 + tig * 2;
            if (MODE == 1) {
                size_t i0 = (size_t)r0 * DD + col;
                size_t i1 = (size_t)(r0 + 8) * DD + col;
                float2 v0 = make_float2(acc[mi][ni][0] + resid[i0], acc[mi][ni][1] + resid[i0 + 1]);
                float2 v1 = make_float2(acc[mi][ni][2] + resid[i1], acc[mi][ni][3] + resid[i1 + 1]);
                *(float2*)&Cf[i0] = v0;
                *(float2*)&Cf[i1] = v1;
            } else {
                if (bn < 2) {
                    // q/k columns -> compact qk buffer
                    *(__nv_bfloat162*)&qk[(size_t)r0 * 256 + col] =
                        __floats2bfloat162_rn(acc[mi][ni][0], acc[mi][ni][1]);
                    *(__nv_bfloat162*)&qk[(size_t)(r0 + 8) * 256 + col] =
                        __floats2bfloat162_rn(acc[mi][ni][2], acc[mi][ni][3]);
                } else {
                    // interleaved (lin, pre) pair -> geglu
                    int e = (col - 256) >> 1;   // geglu output index in [0,2048)
                    float v0 = acc[mi][ni][0] * gelu_exact(acc[mi][ni][1]);
                    float v1 = acc[mi][ni][2] * gelu_exact(acc[mi][ni][3]);
                    if (e < 1024) {
                        concat[(size_t)r0 * EXPD + e] = __float2bfloat16(v0);
                        concat[(size_t)(r0 + 8) * EXPD + e] = __float2bfloat16(v1);
                    } else {
                        vbuf[(size_t)r0 * DD + e - 1024] = __float2bfloat16(v0);
                        vbuf[(size_t)(r0 + 8) * DD + e - 1024] = __float2bfloat16(v1);
                    }
                }
            }
        }
    }
}

// ---------------- flash attention (mma, online softmax) ----------------
// grid (8 q-chunks, B*H); block 256 (8 warps x 16 q rows)
__global__ __launch_bounds__(256, 1) void attn_kernel(const __nv_bfloat16* __restrict__ qk,
                                                      const __nv_bfloat16* __restrict__ vbuf,
                                                      __nv_bfloat16* __restrict__ concat,
                                                      const float* __restrict__ pbm_p,
                                                      const int* __restrict__ fi_p,
                                                      const int* __restrict__ li_p) {
    __shared__ __nv_bfloat16 Ks[128][20];
    __shared__ __nv_bfloat16 Vt[128][136];
    const int tid = threadIdx.x, warp = tid >> 5, lane = tid & 31;
    const int gid = lane >> 2, tig = lane & 3;
    const int bh = blockIdx.y, b = bh >> 3, h = bh & 7;
    const int qbase = blockIdx.x * 128;
    float pbm = *pbm_p;
    const float sp = fmaxf(pbm, 0.f) + log1pf(expf(-fabsf(pbm)));
    int fi = *fi_p; if (fi >= SS) fi = 0;
    int li = *li_p; if (li >= SS) li = 0;

    const int i0 = qbase + warp * 16 + gid;
    const int i1 = i0 + 8;
    uint32_t qa[4];
    {
        const size_t base = ((size_t)(b * SS + i0)) * 256 + h * 16 + tig * 2;
        qa[0] = *(const uint32_t*)&qk[base];
        qa[1] = *(const uint32_t*)&qk[base + 8 * 256];
        qa[2] = *(const uint32_t*)&qk[base + 8];
        qa[3] = *(const uint32_t*)&qk[base + 8 * 256 + 8];
    }
    float m0 = -1e30f, m1 = -1e30f, l0 = 0.f, l1 = 0.f;
    float o[16][4];
#pragma unroll
    for (int ni = 0; ni < 16; ni++)
#pragma unroll
        for (int r = 0; r < 4; r++) o[ni][r] = 0.f;

    const float scale = 0.25f;
    const int qmax = qbase + 127;

    for (int kc = 0; kc < SS / 128; kc++) {
        const int kmin = kc * 128;
        if (kmin > qmax && !((qmax >= fi) && (kmin + 127 >= li))) continue;

        {  // K chunk -> smem [key][16]
            int r = tid >> 1, c = (tid & 1) * 8;
            const uint4 kv = *(const uint4*)&qk[((size_t)(b * SS + kmin + r)) * 256 + 128 + h * 16 + c];
            *(uint2*)&Ks[r][c] = make_uint2(kv.x, kv.y);
            *(uint2*)&Ks[r][c + 4] = make_uint2(kv.z, kv.w);
        }
        {  // V chunk transposed -> smem [dv][key]
            int d2 = (tid & 63) * 2, r0 = tid >> 6;
            const size_t gb = ((size_t)(b * SS + kmin)) * DD + h * 128 + d2;
#pragma unroll
            for (int j = 0; j < 32; j++) {
                int r = r0 + j * 4;
                __nv_bfloat162 vv = *(const __nv_bfloat162*)&vbuf[gb + (size_t)r * DD];
                Vt[d2][r] = vv.x;
                Vt[d2 + 1][r] = vv.y;
            }
        }
        __syncthreads();

        float sc[16][4];
#pragma unroll
        for (int ni = 0; ni < 16; ni++) {
            sc[ni][0] = sc[ni][1] = sc[ni][2] = sc[ni][3] = 0.f;
            uint32_t bfr[2];
            bfr[0] = *(const uint32_t*)&Ks[ni * 8 + gid][tig * 2];
            bfr[1] = *(const uint32_t*)&Ks[ni * 8 + gid][tig * 2 + 8];
            mma16816(sc[ni], qa, bfr);
        }
        float rmax0 = -1e30f, rmax1 = -1e30f;
#pragma unroll
        for (int ni = 0; ni < 16; ni++) {
            int jc = kmin + ni * 8 + tig * 2;
#pragma unroll
            for (int r = 0; r < 4; r++) {
                int j = jc + (r & 1);
                int i = (r < 2) ? i0 : i1;
                bool ok = (j <= i) || ((i >= fi) && (j >= li));
                float s = ok ? fmaf(sc[ni][r], scale, sp * (float)(j - i)) : -1e30f;
                sc[ni][r] = s;
                if (r < 2) rmax0 = fmaxf(rmax0, s);
                else rmax1 = fmaxf(rmax1, s);
            }
        }
        rmax0 = fmaxf(rmax0, __shfl_xor_sync(0xffffffffu, rmax0, 1));
        rmax0 = fmaxf(rmax0, __shfl_xor_sync(0xffffffffu, rmax0, 2));
        rmax1 = fmaxf(rmax1, __shfl_xor_sync(0xffffffffu, rmax1, 1));
        rmax1 = fmaxf(rmax1, __shfl_xor_sync(0xffffffffu, rmax1, 2));
        float mn0 = fmaxf(m0, rmax0), mn1 = fmaxf(m1, rmax1);
        float cor0 = __expf(m0 - mn0), cor1 = __expf(m1 - mn1);
        m0 = mn0; m1 = mn1;
        float rs0 = 0.f, rs1 = 0.f;
#pragma unroll
        for (int ni = 0; ni < 16; ni++) {
            sc[ni][0] = __expf(sc[ni][0] - m0); rs0 += sc[ni][0];
            sc[ni][1] = __expf(sc[ni][1] - m0); rs0 += sc[ni][1];
            sc[ni][2] = __expf(sc[ni][2] - m1); rs1 += sc[ni][2];
            sc[ni][3] = __expf(sc[ni][3] - m1); rs1 += sc[ni][3];
        }
        rs0 += __shfl_xor_sync(0xffffffffu, rs0, 1);
        rs0 += __shfl_xor_sync(0xffffffffu, rs0, 2);
        rs1 += __shfl_xor_sync(0xffffffffu, rs1, 1);
        rs1 += __shfl_xor_sync(0xffffffffu, rs1, 2);
        l0 = l0 * cor0 + rs0;
        l1 = l1 * cor1 + rs1;
#pragma unroll
        for (int ni = 0; ni < 16; ni++) {
            o[ni][0] *= cor0; o[ni][1] *= cor0; o[ni][2] *= cor1; o[ni][3] *= cor1;
        }
#pragma unroll
        for (int ks = 0; ks < 8; ks++) {
            uint32_t pa[4];
            pa[0] = packbf(sc[2 * ks][0], sc[2 * ks][1]);
            pa[1] = packbf(sc[2 * ks][2], sc[2 * ks][3]);
            pa[2] = packbf(sc[2 * ks + 1][0], sc[2 * ks + 1][1]);
            pa[3] = packbf(sc[2 * ks + 1][2], sc[2 * ks + 1][3]);
#pragma unroll
            for (int ni = 0; ni < 16; ni++) {
                uint32_t vb[2];
                const __nv_bfloat16* p = &Vt[ni * 8 + gid][ks * 16 + tig * 2];
                vb[0] = *(const uint32_t*)p;
                vb[1] = *(const uint32_t*)(p + 8);
                mma16816(o[ni], pa, vb);
            }
        }
        __syncthreads();
    }

    float inv0 = 1.f / l0, inv1 = 1.f / l1;
#pragma unroll
    for (int ni = 0; ni < 16; ni++) {
        int col = 1024 + h * 128 + ni * 8 + tig * 2;
        *(__nv_bfloat162*)&concat[((size_t)(b * SS) + i0) * EXPD + col] =
            __floats2bfloat162_rn(o[ni][0] * inv0, o[ni][1] * inv0);
        *(__nv_bfloat162*)&concat[((size_t)(b * SS) + i1) * EXPD + col] =
            __floats2bfloat162_rn(o[ni][2] * inv1, o[ni][3] * inv1);
    }
}

// ---------------- launch ----------------
extern "C" void kernel_launch(void* const* d_in, const int* in_sizes, int n_in,
                              void* d_out, int out_size) {
    const float* x = (const float*)d_in[0];
    const float* norm_w = (const float*)d_in[1];
    const float* expand_w = (const float*)d_in[2];
    const float* project_w = (const float*)d_in[3];
    const float* pbm = (const float*)d_in[4];
    const int* fi = (const int*)d_in[5];
    const int* li = (const int*)d_in[6];
    float* out = (float*)d_out;

    void *p_xn, *p_qk, *p_concat, *p_v, *p_wexp, *p_wproj;
    cudaGetSymbolAddress(&p_xn, g_xn);
    cudaGetSymbolAddress(&p_qk, g_qk);
    cudaGetSymbolAddress(&p_concat, g_concat);
    cudaGetSymbolAddress(&p_v, g_v);
    cudaGetSymbolAddress(&p_wexp, g_wexp);
    cudaGetSymbolAddress(&p_wproj, g_wproj);
    __nv_bfloat16* xn = (__nv_bfloat16*)p_xn;
    __nv_bfloat16* qk = (__nv_bfloat16*)p_qk;
    __nv_bfloat16* concat = (__nv_bfloat16*)p_concat;
    __nv_bfloat16* vb = (__nv_bfloat16*)p_v;
    __nv_bfloat16* wexp = (__nv_bfloat16*)p_wexp;
    __nv_bfloat16* wproj = (__nv_bfloat16*)p_wproj;

    cudaFuncSetAttribute(gemm_bf16<0>, cudaFuncAttributeMaxDynamicSharedMemorySize, GSMEM_BYTES);
    cudaFuncSetAttribute(gemm_bf16<1>, cudaFuncAttributeMaxDynamicSharedMemorySize, GSMEM_BYTES);

    // weights -> bf16 (expand_w with lin/pre interleave reorder)
    cvt_exp_kernel<<<EOUT * (DD / 4) / 256, 256>>>(expand_w, wexp);
    cvt_kernel<<<(DD * EXPD / 4 + 255) / 256, 256>>>(project_w, wproj, DD * EXPD / 4);

    // layernorm
    ln_kernel<<<NROWS, 256>>>(x, norm_w, xn);

    // expand GEMM fused with geglu: writes qk buffer + concat[:, :1024] + vbuf
    gemm_bf16<0><<<dim3(EOUT / 128, NROWS / 128), 256, GSMEM_BYTES>>>(
        xn, wexp, qk, concat, vb, nullptr, nullptr, DD);

    // attention -> concat[:, 1024:2048]
    attn_kernel<<<dim3(SS / 128, BB * HH), 256>>>(qk, vb, concat, pbm, fi, li);

    // project GEMM + residual: out = concat @ wproj^T + x
    gemm_bf16<1><<<dim3(DD / 128, NROWS / 128), 256, GSMEM_BYTES>>>(
        concat, wproj, nullptr, nullptr, nullptr, x, out, EXPD);
}

// round 9
// speedup vs baseline: 1.5083x; 1.0056x over previous
#include <cuda_runtime.h>
#include <cuda_bf16.h>
#include <cstdint>
#include <math.h>

// ---------------- problem constants ----------------
#define BB 16
#define SS 1024
#define DD 1024
#define HH 8
#define QKD 128
#define EXPD 2048
#define NROWS (BB*SS)    // 16384
#define EOUT (2*QKD + 2*EXPD)  // 4352

// ---------------- scratch ----------------
__device__ __nv_bfloat16 g_xn[(size_t)NROWS * DD];
__device__ __nv_bfloat16 g_qk[(size_t)NROWS * 256];       // [q(128) | k(128)]
__device__ __nv_bfloat16 g_concat[(size_t)NROWS * EXPD];  // [0,1024): geglu_local, [1024,2048): attention
__device__ __nv_bfloat16 g_v[(size_t)NROWS * DD];
__device__ __nv_bfloat16 g_wexp[(size_t)EOUT * DD];       // reordered: [q,k | interleaved lin/pre]
__device__ __nv_bfloat16 g_wproj[(size_t)DD * EXPD];

// ---------------- helpers ----------------
__device__ __forceinline__ void mma16816(float d[4], const uint32_t a[4], const uint32_t b[2]) {
    asm volatile(
        "mma.sync.aligned.m16n8k16.row.col.f32.bf16.bf16.f32 "
        "{%0,%1,%2,%3},{%4,%5,%6,%7},{%8,%9},{%0,%1,%2,%3};\n"
        : "+f"(d[0]), "+f"(d[1]), "+f"(d[2]), "+f"(d[3])
        : "r"(a[0]), "r"(a[1]), "r"(a[2]), "r"(a[3]), "r"(b[0]), "r"(b[1]));
}

__device__ __forceinline__ uint32_t packbf(float a, float b) {
    __nv_bfloat162 t = __floats2bfloat162_rn(a, b);
    return *reinterpret_cast<uint32_t*>(&t);
}

__device__ __forceinline__ void ldsm4(uint32_t r[4], uint32_t saddr) {
    asm volatile("ldmatrix.sync.aligned.m8n8.x4.shared.b16 {%0,%1,%2,%3}, [%4];"
                 : "=r"(r[0]), "=r"(r[1]), "=r"(r[2]), "=r"(r[3]) : "r"(saddr));
}

__device__ __forceinline__ void ldsm4t(uint32_t r[4], uint32_t saddr) {
    asm volatile("ldmatrix.sync.aligned.m8n8.x4.trans.shared.b16 {%0,%1,%2,%3}, [%4];"
                 : "=r"(r[0]), "=r"(r[1]), "=r"(r[2]), "=r"(r[3]) : "r"(saddr));
}

__device__ __forceinline__ void cp16(uint32_t saddr, const void* g) {
    asm volatile("cp.async.cg.shared.global [%0], [%1], 16;" :: "r"(saddr), "l"(g));
}

__device__ __forceinline__ float gelu_exact(float p) {
    return 0.5f * p * (1.f + erff(p * 0.70710678118654752f));
}

// ---------------- weight converts ----------------
__global__ void cvt_kernel(const float* __restrict__ src, __nv_bfloat16* __restrict__ dst, int n4) {
    int i = blockIdx.x * blockDim.x + threadIdx.x;
    if (i < n4) {
        float4 v = ((const float4*)src)[i];
        __nv_bfloat162* d = (__nv_bfloat162*)(dst + (size_t)i * 4);
        d[0] = __floats2bfloat162_rn(v.x, v.y);
        d[1] = __floats2bfloat162_rn(v.z, v.w);
    }
}

// expand_w convert + row reorder (lin/pre interleave)
__global__ void cvt_exp_kernel(const float* __restrict__ src, __nv_bfloat16* __restrict__ dst) {
    int i = blockIdx.x * blockDim.x + threadIdx.x;   // over EOUT * (DD/4)
    int r = i >> 8;
    int c4 = i & 255;
    int t = r - 256;
    int sr = (r < 256) ? r : ((t & 1) ? (2304 + (t >> 1)) : (256 + (t >> 1)));
    float4 v = ((const float4*)(src + (size_t)sr * DD))[c4];
    __nv_bfloat162* d = (__nv_bfloat162*)(dst + (size_t)r * DD + c4 * 4);
    d[0] = __floats2bfloat162_rn(v.x, v.y);
    d[1] = __floats2bfloat162_rn(v.z, v.w);
}

// ---------------- LayerNorm ----------------
__global__ __launch_bounds__(256) void ln_kernel(const float* __restrict__ x,
                                                 const float* __restrict__ w,
                                                 __nv_bfloat16* __restrict__ out) {
    int row = blockIdx.x;
    float4 v = ((const float4*)(x + (size_t)row * DD))[threadIdx.x];
    float s = v.x + v.y + v.z + v.w;
    float s2 = v.x * v.x + v.y * v.y + v.z * v.z + v.w * v.w;
#pragma unroll
    for (int o = 16; o; o >>= 1) {
        s += __shfl_xor_sync(0xffffffffu, s, o);
        s2 += __shfl_xor_sync(0xffffffffu, s2, o);
    }
    __shared__ float rs[8], rs2[8];
    int warp = threadIdx.x >> 5, lane = threadIdx.x & 31;
    if (!lane) { rs[warp] = s; rs2[warp] = s2; }
    __syncthreads();
    if (threadIdx.x == 0) {
        float a = 0.f, b = 0.f;
#pragma unroll
        for (int i = 0; i < 8; i++) { a += rs[i]; b += rs2[i]; }
        rs[0] = a; rs2[0] = b;
    }
    __syncthreads();
    float mu = rs[0] * (1.f / DD);
    float var = rs2[0] * (1.f / DD) - mu * mu;
    float r = rsqrtf(var + 1e-5f);
    float4 w4 = ((const float4*)w)[threadIdx.x];
    __nv_bfloat16* op = out + (size_t)row * DD + threadIdx.x * 4;
    *(__nv_bfloat162*)op = __floats2bfloat162_rn((v.x - mu) * r * w4.x, (v.y - mu) * r * w4.y);
    *(__nv_bfloat162*)(op + 2) = __floats2bfloat162_rn((v.z - mu) * r * w4.z, (v.w - mu) * r * w4.w);
}

// ---------------- bf16 GEMM: C[M,N] = A[M,K] * Bw[N,K]^T ----------------
// CTA tile BM=256, BN=128, BK=64; 8 warps as 4x2, warp tile 64x64 (4x8 m16n8k16).
// 3-stage cp.async pipeline, ldmatrix.x4, XOR-swizzled smem.
#define GSTG 3
#define A_ST (256 * 128)                 // bytes per A stage
#define B_ST (128 * 128)
#define STB (A_ST + B_ST)                // 48 KB
#define GSMEM_BYTES (GSTG * STB)         // 144 KB

template <int MODE>
__global__ __launch_bounds__(256, 1) void gemm_bf16(const __nv_bfloat16* __restrict__ A,
                                                    const __nv_bfloat16* __restrict__ Bw,
                                                    __nv_bfloat16* __restrict__ qk,
                                                    __nv_bfloat16* __restrict__ concat,
                                                    __nv_bfloat16* __restrict__ vbuf,
                                                    const float* __restrict__ resid,
                                                    float* __restrict__ Cf,
                                                    int K) {
    extern __shared__ __nv_bfloat16 smbuf[];
    const int tid = threadIdx.x;
    const int warp = tid >> 5, lane = tid & 31;
    const int gid = lane >> 2, tig = lane & 3;
    const int wm = (warp >> 1) * 64, wn = (warp & 1) * 64;
    const int bm = blockIdx.y, bn = blockIdx.x;

    const uint32_t sbase = (uint32_t)__cvta_generic_to_shared(smbuf);

    const int r = tid >> 3, c = tid & 7;
    const int swz = (c ^ (r & 7)) * 16;
    const __nv_bfloat16* Ag = A + ((size_t)(bm * 256 + r)) * K + c * 8;
    const __nv_bfloat16* Bg = Bw + ((size_t)(bn * 128 + r)) * K + c * 8;

    auto load_stage = [&](int s, int kt) {
        uint32_t sa = sbase + s * STB + r * 128 + swz;
        uint32_t sb = sbase + s * STB + A_ST + r * 128 + swz;
        const __nv_bfloat16* ag = Ag + kt * 64;
        const __nv_bfloat16* bg = Bg + kt * 64;
#pragma unroll
        for (int j = 0; j < 8; j++) cp16(sa + j * 32 * 128, ag + (size_t)(j * 32) * K);
#pragma unroll
        for (int j = 0; j < 4; j++) cp16(sb + j * 32 * 128, bg + (size_t)(j * 32) * K);
    };

    float acc[4][8][4];
#pragma unroll
    for (int i = 0; i < 4; i++)
#pragma unroll
        for (int j = 0; j < 8; j++)
#pragma unroll
            for (int q = 0; q < 4; q++) acc[i][j][q] = 0.f;

    load_stage(0, 0);
    asm volatile("cp.async.commit_group;" ::: "memory");
    load_stage(1, 1);
    asm volatile("cp.async.commit_group;" ::: "memory");

    const int a_lrow = lane & 15;
    const int a_chi = lane >> 4;
    const int b_lrow = (lane & 7) + ((lane >> 4) << 3);
    const int b_chi = (lane >> 3) & 1;

    const int KT = K >> 6;
    for (int kt = 0; kt < KT; kt++) {
        asm volatile("cp.async.wait_group 1;" ::: "memory");
        __syncthreads();
        if (kt + 2 < KT) load_stage((kt + 2) % GSTG, kt + 2);
        asm volatile("cp.async.commit_group;" ::: "memory");

        const uint32_t sA = sbase + (kt % GSTG) * STB;
        const uint32_t sB = sA + A_ST;
#pragma unroll
        for (int ks = 0; ks < 4; ks++) {
            uint32_t af[4][4], bfr[8][2];
#pragma unroll
            for (int mi = 0; mi < 4; mi++) {
                int row = wm + mi * 16 + a_lrow;
                int cc = ks * 2 + a_chi;
                ldsm4(af[mi], sA + row * 128 + ((cc ^ (row & 7)) * 16));
            }
#pragma unroll
            for (int j = 0; j < 4; j++) {
                int row = wn + j * 16 + b_lrow;
                int cc = ks * 2 + b_chi;
                uint32_t rr[4];
                ldsm4(rr, sB + row * 128 + ((cc ^ (row & 7)) * 16));
                bfr[j * 2][0] = rr[0]; bfr[j * 2][1] = rr[1];
                bfr[j * 2 + 1][0] = rr[2]; bfr[j * 2 + 1][1] = rr[3];
            }
#pragma unroll
            for (int mi = 0; mi < 4; mi++)
#pragma unroll
                for (int ni = 0; ni < 8; ni++) mma16816(acc[mi][ni], af[mi], bfr[ni]);
        }
        __syncthreads();
    }

#pragma unroll
    for (int mi = 0; mi < 4; mi++) {
        int r0 = bm * 256 + wm + mi * 16 + gid;
#pragma unroll
        for (int ni = 0; ni < 8; ni++) {
            int col = bn * 128 + wn + ni * 8 + tig * 2;
            if (MODE == 1) {
                size_t i0 = (size_t)r0 * DD + col;
                size_t i1 = (size_t)(r0 + 8) * DD + col;
                float2 v0 = make_float2(acc[mi][ni][0] + resid[i0], acc[mi][ni][1] + resid[i0 + 1]);
                float2 v1 = make_float2(acc[mi][ni][2] + resid[i1], acc[mi][ni][3] + resid[i1 + 1]);
                *(float2*)&Cf[i0] = v0;
                *(float2*)&Cf[i1] = v1;
            } else {
                if (bn < 2) {
                    *(__nv_bfloat162*)&qk[(size_t)r0 * 256 + col] =
                        __floats2bfloat162_rn(acc[mi][ni][0], acc[mi][ni][1]);
                    *(__nv_bfloat162*)&qk[(size_t)(r0 + 8) * 256 + col] =
                        __floats2bfloat162_rn(acc[mi][ni][2], acc[mi][ni][3]);
                } else {
                    int e = (col - 256) >> 1;
                    float v0 = acc[mi][ni][0] * gelu_exact(acc[mi][ni][1]);
                    float v1 = acc[mi][ni][2] * gelu_exact(acc[mi][ni][3]);
                    if (e < 1024) {
                        concat[(size_t)r0 * EXPD + e] = __float2bfloat16(v0);
                        concat[(size_t)(r0 + 8) * EXPD + e] = __float2bfloat16(v1);
                    } else {
                        vbuf[(size_t)r0 * DD + e - 1024] = __float2bfloat16(v0);
                        vbuf[(size_t)(r0 + 8) * DD + e - 1024] = __float2bfloat16(v1);
                    }
                }
            }
        }
    }
}

// ---------------- flash attention (mma, online softmax, ldmatrix.trans V) ----------------
// grid (8 q-chunks, B*H); block 256 (8 warps x 16 q rows)
__global__ __launch_bounds__(256, 1) void attn_kernel(const __nv_bfloat16* __restrict__ qk,
                                                      const __nv_bfloat16* __restrict__ vbuf,
                                                      __nv_bfloat16* __restrict__ concat,
                                                      const float* __restrict__ pbm_p,
                                                      const int* __restrict__ fi_p,
                                                      const int* __restrict__ li_p) {
    __shared__ __align__(16) __nv_bfloat16 Ks[128][24];          // 32B K rows at 48B stride
    __shared__ __align__(16) __nv_bfloat16 Vs[128 * 128];        // [key][dv], XOR-swizzled 16B chunks
    const int tid = threadIdx.x, warp = tid >> 5, lane = tid & 31;
    const int gid = lane >> 2, tig = lane & 3;
    const int bh = blockIdx.y, b = bh >> 3, h = bh & 7;
    const int qbase = blockIdx.x * 128;
    float pbm = *pbm_p;
    const float sp = fmaxf(pbm, 0.f) + log1pf(expf(-fabsf(pbm)));
    int fi = *fi_p; if (fi >= SS) fi = 0;
    int li = *li_p; if (li >= SS) li = 0;

    const uint32_t ksbase = (uint32_t)__cvta_generic_to_shared(Ks);
    const uint32_t vsbase = (uint32_t)__cvta_generic_to_shared(Vs);

    const int i0 = qbase + warp * 16 + gid;
    const int i1 = i0 + 8;
    uint32_t qa[4];
    {
        const size_t base = ((size_t)(b * SS + i0)) * 256 + h * 16 + tig * 2;
        qa[0] = *(const uint32_t*)&qk[base];
        qa[1] = *(const uint32_t*)&qk[base + 8 * 256];
        qa[2] = *(const uint32_t*)&qk[base + 8];
        qa[3] = *(const uint32_t*)&qk[base + 8 * 256 + 8];
    }
    float m0 = -1e30f, m1 = -1e30f, l0 = 0.f, l1 = 0.f;
    float o[16][4];
#pragma unroll
    for (int ni = 0; ni < 16; ni++)
#pragma unroll
        for (int r = 0; r < 4; r++) o[ni][r] = 0.f;

    const float scale = 0.25f;
    const int qmax = qbase + 127;
    const int l15 = lane & 15, lhi = lane >> 4;
    const uint32_t vrow = vsbase + l15 * 256;

    for (int kc = 0; kc < SS / 128; kc++) {
        const int kmin = kc * 128;
        if (kmin > qmax && !((qmax >= fi) && (kmin + 127 >= li))) continue;

        // K chunk: 128 rows x 32B (two 16B cp.async per row; 256 threads)
        {
            int row = tid >> 1, half = tid & 1;
            cp16(ksbase + row * 48 + half * 16,
                 &qk[((size_t)(b * SS + kmin + row)) * 256 + 128 + h * 16 + half * 8]);
        }
        // V chunk: row-major [key][dv], 16B chunks XOR-swizzled by (row & 15)
        {
            int row = tid >> 1, half = tid & 1;
            const __nv_bfloat16* src = &vbuf[((size_t)(b * SS + kmin + row)) * DD + h * 128 + half * 64];
            uint32_t drow = vsbase + row * 256;
            int rsw = row & 15;
#pragma unroll
            for (int j = 0; j < 8; j++) {
                int cchunk = half * 8 + j;
                cp16(drow + ((cchunk ^ rsw) << 4), src + j * 8);
            }
        }
        asm volatile("cp.async.commit_group;" ::: "memory");
        asm volatile("cp.async.wait_group 0;" ::: "memory");
        __syncthreads();

        float sc[16][4];
#pragma unroll
        for (int ni = 0; ni < 16; ni++) {
            sc[ni][0] = sc[ni][1] = sc[ni][2] = sc[ni][3] = 0.f;
            uint32_t bfr[2];
            bfr[0] = *(const uint32_t*)&Ks[ni * 8 + gid][tig * 2];
            bfr[1] = *(const uint32_t*)&Ks[ni * 8 + gid][tig * 2 + 8];
            mma16816(sc[ni], qa, bfr);
        }
        float rmax0 = -1e30f, rmax1 = -1e30f;
#pragma unroll
        for (int ni = 0; ni < 16; ni++) {
            int jc = kmin + ni * 8 + tig * 2;
#pragma unroll
            for (int r = 0; r < 4; r++) {
                int j = jc + (r & 1);
                int i = (r < 2) ? i0 : i1;
                bool ok = (j <= i) || ((i >= fi) && (j >= li));
                float s = ok ? fmaf(sc[ni][r], scale, sp * (float)(j - i)) : -1e30f;
                sc[ni][r] = s;
                if (r < 2) rmax0 = fmaxf(rmax0, s);
                else rmax1 = fmaxf(rmax1, s);
            }
        }
        rmax0 = fmaxf(rmax0, __shfl_xor_sync(0xffffffffu, rmax0, 1));
        rmax0 = fmaxf(rmax0, __shfl_xor_sync(0xffffffffu, rmax0, 2));
        rmax1 = fmaxf(rmax1, __shfl_xor_sync(0xffffffffu, rmax1, 1));
        rmax1 = fmaxf(rmax1, __shfl_xor_sync(0xffffffffu, rmax1, 2));
        float mn0 = fmaxf(m0, rmax0), mn1 = fmaxf(m1, rmax1);
        float cor0 = __expf(m0 - mn0), cor1 = __expf(m1 - mn1);
        m0 = mn0; m1 = mn1;
        float rs0 = 0.f, rs1 = 0.f;
#pragma unroll
        for (int ni = 0; ni < 16; ni++) {
            sc[ni][0] = __expf(sc[ni][0] - m0); rs0 += sc[ni][0];
            sc[ni][1] = __expf(sc[ni][1] - m0); rs0 += sc[ni][1];
            sc[ni][2] = __expf(sc[ni][2] - m1); rs1 += sc[ni][2];
            sc[ni][3] = __expf(sc[ni][3] - m1); rs1 += sc[ni][3];
        }
        rs0 += __shfl_xor_sync(0xffffffffu, rs0, 1);
        rs0 += __shfl_xor_sync(0xffffffffu, rs0, 2);
        rs1 += __shfl_xor_sync(0xffffffffu, rs1, 1);
        rs1 += __shfl_xor_sync(0xffffffffu, rs1, 2);
        l0 = l0 * cor0 + rs0;
        l1 = l1 * cor1 + rs1;
#pragma unroll
        for (int ni = 0; ni < 16; ni++) {
            o[ni][0] *= cor0; o[ni][1] *= cor0; o[ni][2] *= cor1; o[ni][3] *= cor1;
        }
        // PV: B fragments via ldmatrix.x4.trans from row-major swizzled Vs
#pragma unroll
        for (int ks = 0; ks < 8; ks++) {
            uint32_t pa[4];
            pa[0] = packbf(sc[2 * ks][0], sc[2 * ks][1]);
            pa[1] = packbf(sc[2 * ks][2], sc[2 * ks][3]);
            pa[2] = packbf(sc[2 * ks + 1][0], sc[2 * ks + 1][1]);
            pa[3] = packbf(sc[2 * ks + 1][2], sc[2 * ks + 1][3]);
            const uint32_t kofs = vrow + ks * 4096;
#pragma unroll
            for (int ni2 = 0; ni2 < 8; ni2++) {
                uint32_t rr[4];
                ldsm4t(rr, kofs + (((ni2 * 2 + lhi) ^ l15) << 4));
                uint32_t b0[2] = {rr[0], rr[1]};
                uint32_t b1[2] = {rr[2], rr[3]};
                mma16816(o[2 * ni2], pa, b0);
                mma16816(o[2 * ni2 + 1], pa, b1);
            }
        }
        __syncthreads();
    }

    float inv0 = 1.f / l0, inv1 = 1.f / l1;
#pragma unroll
    for (int ni = 0; ni < 16; ni++) {
        int col = 1024 + h * 128 + ni * 8 + tig * 2;
        *(__nv_bfloat162*)&concat[((size_t)(b * SS) + i0) * EXPD + col] =
            __floats2bfloat162_rn(o[ni][0] * inv0, o[ni][1] * inv0);
        *(__nv_bfloat162*)&concat[((size_t)(b * SS) + i1) * EXPD + col] =
            __floats2bfloat162_rn(o[ni][2] * inv1, o[ni][3] * inv1);
    }
}

// ---------------- launch ----------------
extern "C" void kernel_launch(void* const* d_in, const int* in_sizes, int n_in,
                              void* d_out, int out_size) {
    const float* x = (const float*)d_in[0];
    const float* norm_w = (const float*)d_in[1];
    const float* expand_w = (const float*)d_in[2];
    const float* project_w = (const float*)d_in[3];
    const float* pbm = (const float*)d_in[4];
    const int* fi = (const int*)d_in[5];
    const int* li = (const int*)d_in[6];
    float* out = (float*)d_out;

    void *p_xn, *p_qk, *p_concat, *p_v, *p_wexp, *p_wproj;
    cudaGetSymbolAddress(&p_xn, g_xn);
    cudaGetSymbolAddress(&p_qk, g_qk);
    cudaGetSymbolAddress(&p_concat, g_concat);
    cudaGetSymbolAddress(&p_v, g_v);
    cudaGetSymbolAddress(&p_wexp, g_wexp);
    cudaGetSymbolAddress(&p_wproj, g_wproj);
    __nv_bfloat16* xn = (__nv_bfloat16*)p_xn;
    __nv_bfloat16* qk = (__nv_bfloat16*)p_qk;
    __nv_bfloat16* concat = (__nv_bfloat16*)p_concat;
    __nv_bfloat16* vb = (__nv_bfloat16*)p_v;
    __nv_bfloat16* wexp = (__nv_bfloat16*)p_wexp;
    __nv_bfloat16* wproj = (__nv_bfloat16*)p_wproj;

    cudaFuncSetAttribute(gemm_bf16<0>, cudaFuncAttributeMaxDynamicSharedMemorySize, GSMEM_BYTES);
    cudaFuncSetAttribute(gemm_bf16<1>, cudaFuncAttributeMaxDynamicSharedMemorySize, GSMEM_BYTES);

    // weights -> bf16
    cvt_exp_kernel<<<EOUT * (DD / 4) / 256, 256>>>(expand_w, wexp);
    cvt_kernel<<<(DD * EXPD / 4 + 255) / 256, 256>>>(project_w, wproj, DD * EXPD / 4);

    // layernorm
    ln_kernel<<<NROWS, 256>>>(x, norm_w, xn);

    // expand GEMM fused with geglu: writes qk buffer + concat[:, :1024] + vbuf
    gemm_bf16<0><<<dim3(EOUT / 128, NROWS / 256), 256, GSMEM_BYTES>>>(
        xn, wexp, qk, concat, vb, nullptr, nullptr, DD);

    // attention -> concat[:, 1024:2048]
    attn_kernel<<<dim3(SS / 128, BB * HH), 256>>>(qk, vb, concat, pbm, fi, li);

    // project GEMM + residual: out = concat @ wproj^T + x
    gemm_bf16<1><<<dim3(DD / 128, NROWS / 256), 256, GSMEM_BYTES>>>(
        concat, wproj, nullptr, nullptr, nullptr, x, out, EXPD);
}

// round 10
// speedup vs baseline: 1.6200x; 1.0741x over previous
#include <cuda_runtime.h>
#include <cuda_bf16.h>
#include <cuda_fp16.h>
#include <cstdint>
#include <math.h>

// ---------------- problem constants ----------------
#define BB 16
#define SS 1024
#define DD 1024
#define HH 8
#define QKD 128
#define EXPD 2048
#define NROWS (BB*SS)    // 16384
#define EOUT (2*QKD + 2*EXPD)  // 4352
#define LOG2E 1.4426950408889634f

// ---------------- scratch ----------------
__device__ __nv_bfloat16 g_xn[(size_t)NROWS * DD];
__device__ __nv_bfloat16 g_qk[(size_t)NROWS * 256];       // [q(128, pre-scaled by 0.25*log2e) | k(128)]
__device__ __nv_bfloat16 g_concat[(size_t)NROWS * EXPD];  // [0,1024): geglu_local, [1024,2048): attention
__device__ __half g_v[(size_t)NROWS * DD];                // V in f16
__device__ __nv_bfloat16 g_wexp[(size_t)EOUT * DD];       // reordered: [q,k | interleaved lin/pre]
__device__ __nv_bfloat16 g_wproj[(size_t)DD * EXPD];

// ---------------- helpers ----------------
__device__ __forceinline__ void mma16816(float d[4], const uint32_t a[4], const uint32_t b[2]) {
    asm volatile(
        "mma.sync.aligned.m16n8k16.row.col.f32.bf16.bf16.f32 "
        "{%0,%1,%2,%3},{%4,%5,%6,%7},{%8,%9},{%0,%1,%2,%3};\n"
        : "+f"(d[0]), "+f"(d[1]), "+f"(d[2]), "+f"(d[3])
        : "r"(a[0]), "r"(a[1]), "r"(a[2]), "r"(a[3]), "r"(b[0]), "r"(b[1]));
}

__device__ __forceinline__ void mma16816h(float d[4], const uint32_t a[4], const uint32_t b[2]) {
    asm volatile(
        "mma.sync.aligned.m16n8k16.row.col.f32.f16.f16.f32 "
        "{%0,%1,%2,%3},{%4,%5,%6,%7},{%8,%9},{%0,%1,%2,%3};\n"
        : "+f"(d[0]), "+f"(d[1]), "+f"(d[2]), "+f"(d[3])
        : "r"(a[0]), "r"(a[1]), "r"(a[2]), "r"(a[3]), "r"(b[0]), "r"(b[1]));
}

__device__ __forceinline__ void ldsm4(uint32_t r[4], uint32_t saddr) {
    asm volatile("ldmatrix.sync.aligned.m8n8.x4.shared.b16 {%0,%1,%2,%3}, [%4];"
                 : "=r"(r[0]), "=r"(r[1]), "=r"(r[2]), "=r"(r[3]) : "r"(saddr));
}

__device__ __forceinline__ void ldsm4t(uint32_t r[4], uint32_t saddr) {
    asm volatile("ldmatrix.sync.aligned.m8n8.x4.trans.shared.b16 {%0,%1,%2,%3}, [%4];"
                 : "=r"(r[0]), "=r"(r[1]), "=r"(r[2]), "=r"(r[3]) : "r"(saddr));
}

__device__ __forceinline__ void cp16(uint32_t saddr, const void* g) {
    asm volatile("cp.async.cg.shared.global [%0], [%1], 16;" :: "r"(saddr), "l"(g));
}

// exp2 of two f32 values -> packed f16x2 probabilities
__device__ __forceinline__ uint32_t exp2_f16x2(float lo, float hi) {
    uint32_t u, p;
    asm("cvt.rn.f16x2.f32 %0, %1, %2;" : "=r"(u) : "f"(hi), "f"(lo));
    asm("ex2.approx.f16x2 %0, %1;" : "=r"(p) : "r"(u));
    return p;
}

__device__ __forceinline__ float gelu_exact(float p) {
    return 0.5f * p * (1.f + erff(p * 0.70710678118654752f));
}

// ---------------- weight converts ----------------
__global__ void cvt_kernel(const float* __restrict__ src, __nv_bfloat16* __restrict__ dst, int n4) {
    int i = blockIdx.x * blockDim.x + threadIdx.x;
    if (i < n4) {
        float4 v = ((const float4*)src)[i];
        __nv_bfloat162* d = (__nv_bfloat162*)(dst + (size_t)i * 4);
        d[0] = __floats2bfloat162_rn(v.x, v.y);
        d[1] = __floats2bfloat162_rn(v.z, v.w);
    }
}

// expand_w convert + row reorder (lin/pre interleave)
__global__ void cvt_exp_kernel(const float* __restrict__ src, __nv_bfloat16* __restrict__ dst) {
    int i = blockIdx.x * blockDim.x + threadIdx.x;   // over EOUT * (DD/4)
    int r = i >> 8;
    int c4 = i & 255;
    int t = r - 256;
    int sr = (r < 256) ? r : ((t & 1) ? (2304 + (t >> 1)) : (256 + (t >> 1)));
    float4 v = ((const float4*)(src + (size_t)sr * DD))[c4];
    __nv_bfloat162* d = (__nv_bfloat162*)(dst + (size_t)r * DD + c4 * 4);
    d[0] = __floats2bfloat162_rn(v.x, v.y);
    d[1] = __floats2bfloat162_rn(v.z, v.w);
}

// ---------------- LayerNorm ----------------
__global__ __launch_bounds__(256) void ln_kernel(const float* __restrict__ x,
                                                 const float* __restrict__ w,
                                                 __nv_bfloat16* __restrict__ out) {
    int row = blockIdx.x;
    float4 v = ((const float4*)(x + (size_t)row * DD))[threadIdx.x];
    float s = v.x + v.y + v.z + v.w;
    float s2 = v.x * v.x + v.y * v.y + v.z * v.z + v.w * v.w;
#pragma unroll
    for (int o = 16; o; o >>= 1) {
        s += __shfl_xor_sync(0xffffffffu, s, o);
        s2 += __shfl_xor_sync(0xffffffffu, s2, o);
    }
    __shared__ float rs[8], rs2[8];
    int warp = threadIdx.x >> 5, lane = threadIdx.x & 31;
    if (!lane) { rs[warp] = s; rs2[warp] = s2; }
    __syncthreads();
    if (threadIdx.x == 0) {
        float a = 0.f, b = 0.f;
#pragma unroll
        for (int i = 0; i < 8; i++) { a += rs[i]; b += rs2[i]; }
        rs[0] = a; rs2[0] = b;
    }
    __syncthreads();
    float mu = rs[0] * (1.f / DD);
    float var = rs2[0] * (1.f / DD) - mu * mu;
    float r = rsqrtf(var + 1e-5f);
    float4 w4 = ((const float4*)w)[threadIdx.x];
    __nv_bfloat16* op = out + (size_t)row * DD + threadIdx.x * 4;
    *(__nv_bfloat162*)op = __floats2bfloat162_rn((v.x - mu) * r * w4.x, (v.y - mu) * r * w4.y);
    *(__nv_bfloat162*)(op + 2) = __floats2bfloat162_rn((v.z - mu) * r * w4.z, (v.w - mu) * r * w4.w);
}

// ---------------- bf16 GEMM (round-7 proven shape): C[M,N] = A[M,K]*Bw[N,K]^T ----------------
// BM=128, BN=128, BK=64, 256 threads, warps 2x4, warp tile 64x32, 3-stage cp.async.
#define GSTG 3
#define GSTAGE_BYTES (128 * 64 * 2)
#define GSMEM_BYTES (2 * GSTG * GSTAGE_BYTES)

template <int MODE>
__global__ __launch_bounds__(256, 2) void gemm_bf16(const __nv_bfloat16* __restrict__ A,
                                                    const __nv_bfloat16* __restrict__ Bw,
                                                    __nv_bfloat16* __restrict__ qk,
                                                    __nv_bfloat16* __restrict__ concat,
                                                    __half* __restrict__ vbuf,
                                                    const float* __restrict__ resid,
                                                    float* __restrict__ Cf,
                                                    int K) {
    extern __shared__ __nv_bfloat16 smbuf[];
    const int tid = threadIdx.x;
    const int warp = tid >> 5, lane = tid & 31;
    const int gid = lane >> 2, tig = lane & 3;
    const int wm = (warp >> 2) * 64, wn = (warp & 3) * 32;
    const int bm = blockIdx.y, bn = blockIdx.x;

    const uint32_t sbase = (uint32_t)__cvta_generic_to_shared(smbuf);

    const int r = tid >> 3, c = tid & 7;
    const int swz = (c ^ (r & 7)) * 16;
    const __nv_bfloat16* Ag = A + ((size_t)(bm * 128 + r)) * K + c * 8;
    const __nv_bfloat16* Bg = Bw + ((size_t)(bn * 128 + r)) * K + c * 8;

    auto load_stage = [&](int s, int kt) {
        uint32_t sa = sbase + s * GSTAGE_BYTES + r * 128 + swz;
        uint32_t sb = sbase + GSTG * GSTAGE_BYTES + s * GSTAGE_BYTES + r * 128 + swz;
        const __nv_bfloat16* ag = Ag + kt * 64;
        const __nv_bfloat16* bg = Bg + kt * 64;
#pragma unroll
        for (int it = 0; it < 4; it++) {
            cp16(sa + it * 32 * 128, ag + (size_t)(it * 32) * K);
            cp16(sb + it * 32 * 128, bg + (size_t)(it * 32) * K);
        }
    };

    float acc[4][4][4];
#pragma unroll
    for (int i = 0; i < 4; i++)
#pragma unroll
        for (int j = 0; j < 4; j++)
#pragma unroll
            for (int q = 0; q < 4; q++) acc[i][j][q] = 0.f;

    load_stage(0, 0);
    asm volatile("cp.async.commit_group;" ::: "memory");
    load_stage(1, 1);
    asm volatile("cp.async.commit_group;" ::: "memory");

    const int a_lrow = lane & 15;
    const int a_chi = lane >> 4;
    const int b_lrow = (lane & 7) + ((lane >> 4) << 3);
    const int b_chi = (lane >> 3) & 1;

    const int KT = K >> 6;
    for (int kt = 0; kt < KT; kt++) {
        asm volatile("cp.async.wait_group 1;" ::: "memory");
        __syncthreads();
        if (kt + 2 < KT) load_stage((kt + 2) % GSTG, kt + 2);
        asm volatile("cp.async.commit_group;" ::: "memory");

        const uint32_t sA = sbase + (kt % GSTG) * GSTAGE_BYTES;
        const uint32_t sB = sA + GSTG * GSTAGE_BYTES;
#pragma unroll
        for (int ks = 0; ks < 4; ks++) {
            uint32_t af[4][4], bfr[4][2];
#pragma unroll
            for (int mi = 0; mi < 4; mi++) {
                int row = wm + mi * 16 + a_lrow;
                int cc = ks * 2 + a_chi;
                ldsm4(af[mi], sA + row * 128 + ((cc ^ (row & 7)) * 16));
            }
#pragma unroll
            for (int j = 0; j < 2; j++) {
                int row = wn + j * 16 + b_lrow;
                int cc = ks * 2 + b_chi;
                uint32_t rr[4];
                ldsm4(rr, sB + row * 128 + ((cc ^ (row & 7)) * 16));
                bfr[j * 2][0] = rr[0]; bfr[j * 2][1] = rr[1];
                bfr[j * 2 + 1][0] = rr[2]; bfr[j * 2 + 1][1] = rr[3];
            }
#pragma unroll
            for (int mi = 0; mi < 4; mi++)
#pragma unroll
                for (int ni = 0; ni < 4; ni++) mma16816(acc[mi][ni], af[mi], bfr[ni]);
        }
        // NOTE: no trailing __syncthreads — next iteration's wait+sync orders buffer reuse.
    }

    const float QSCALE = 0.25f * LOG2E;  // fold attention scale + log2e into q
#pragma unroll
    for (int mi = 0; mi < 4; mi++) {
        int r0 = bm * 128 + wm + mi * 16 + gid;
#pragma unroll
        for (int ni = 0; ni < 4; ni++) {
            int col = bn * 128 + wn + ni * 8 + tig * 2;
            if (MODE == 1) {
                size_t i0 = (size_t)r0 * DD + col;
                size_t i1 = (size_t)(r0 + 8) * DD + col;
                float2 v0 = make_float2(acc[mi][ni][0] + resid[i0], acc[mi][ni][1] + resid[i0 + 1]);
                float2 v1 = make_float2(acc[mi][ni][2] + resid[i1], acc[mi][ni][3] + resid[i1 + 1]);
                *(float2*)&Cf[i0] = v0;
                *(float2*)&Cf[i1] = v1;
            } else {
                if (bn < 2) {
                    float f = (bn == 0) ? QSCALE : 1.f;   // bn==0 -> q columns
                    *(__nv_bfloat162*)&qk[(size_t)r0 * 256 + col] =
                        __floats2bfloat162_rn(acc[mi][ni][0] * f, acc[mi][ni][1] * f);
                    *(__nv_bfloat162*)&qk[(size_t)(r0 + 8) * 256 + col] =
                        __floats2bfloat162_rn(acc[mi][ni][2] * f, acc[mi][ni][3] * f);
                } else {
                    int e = (col - 256) >> 1;
                    float v0 = acc[mi][ni][0] * gelu_exact(acc[mi][ni][1]);
                    float v1 = acc[mi][ni][2] * gelu_exact(acc[mi][ni][3]);
                    if (e < 1024) {
                        concat[(size_t)r0 * EXPD + e] = __float2bfloat16(v0);
                        concat[(size_t)(r0 + 8) * EXPD + e] = __float2bfloat16(v1);
                    } else {
                        vbuf[(size_t)r0 * DD + e - 1024] = __float2half(v0);
                        vbuf[(size_t)(r0 + 8) * DD + e - 1024] = __float2half(v1);
                    }
                }
            }
        }
    }
}

// ---------------- flash attention: log2-domain softmax, f16x2 exp, f16 PV, ones-column sums ----
// grid (8 q-chunks, B*H); block 256 (8 warps x 16 q rows); double-buffered K/V chunks.
#define AKS_B 6144                         // Ks stage: 128 rows * 48B
#define AVS_B 32768                        // Vs stage: 128 rows * 256B
#define AST_B (AKS_B + AVS_B)              // 38912 per stage
#define ATT_SMEM (2 * AST_B)               // 77824

__global__ __launch_bounds__(256, 1) void attn_kernel(const __nv_bfloat16* __restrict__ qk,
                                                      const __half* __restrict__ vbuf,
                                                      __nv_bfloat16* __restrict__ concat,
                                                      const float* __restrict__ pbm_p,
                                                      const int* __restrict__ fi_p,
                                                      const int* __restrict__ li_p) {
    extern __shared__ __align__(16) char asmem[];
    const int tid = threadIdx.x, warp = tid >> 5, lane = tid & 31;
    const int gid = lane >> 2, tig = lane & 3;
    const int bh = blockIdx.y, b = bh >> 3, h = bh & 7;
    const int qch = blockIdx.x;
    const int qbase = qch * 128;
    float pbm = *pbm_p;
    const float sp_l2 = (fmaxf(pbm, 0.f) + log1pf(expf(-fabsf(pbm)))) * LOG2E;
    int fi = *fi_p; if (fi >= SS) fi = 0;
    int li = *li_p; if (li >= SS) li = 0;

    const uint32_t abase = (uint32_t)__cvta_generic_to_shared(asmem);

    const int i0 = qbase + warp * 16 + gid;
    const int i1 = i0 + 8;
    uint32_t qa[4];
    {
        const size_t base = ((size_t)(b * SS + i0)) * 256 + h * 16 + tig * 2;
        qa[0] = *(const uint32_t*)&qk[base];
        qa[1] = *(const uint32_t*)&qk[base + 8 * 256];
        qa[2] = *(const uint32_t*)&qk[base + 8];
        qa[3] = *(const uint32_t*)&qk[base + 8 * 256 + 8];
    }
    float m0 = -1e30f, m1 = -1e30f;
    float o[16][4];
#pragma unroll
    for (int ni = 0; ni < 16; ni++)
#pragma unroll
        for (int r = 0; r < 4; r++) o[ni][r] = 0.f;
    float o_l[4] = {0.f, 0.f, 0.f, 0.f};  // ones-column accumulator: row sums

    const int qmax = qbase + 127;
    const int l15 = lane & 15, lhi = lane >> 4;

    // chunk list: [0..qch] plus override tail
    int list[8];
    int n = 0;
#pragma unroll
    for (int kc = 0; kc < 8; kc++) {
        int kmin = kc * 128;
        if (kmin <= qmax || ((qmax >= fi) && (kmin + 127 >= li))) list[n++] = kc;
    }

    const int lrow = tid >> 1, lhalf = tid & 1;
    auto load_chunk = [&](int st, int kmin) {
        uint32_t ks = abase + st * AST_B;
        uint32_t vs = ks + AKS_B;
        cp16(ks + lrow * 48 + lhalf * 16,
             &qk[((size_t)(b * SS + kmin + lrow)) * 256 + 128 + h * 16 + lhalf * 8]);
        const __half* src = &vbuf[((size_t)(b * SS + kmin + lrow)) * DD + h * 128 + lhalf * 64];
        uint32_t drow = vs + lrow * 256;
        int rsw = lrow & 15;
#pragma unroll
        for (int j = 0; j < 8; j++) {
            int cc = lhalf * 8 + j;
            cp16(drow + ((cc ^ rsw) << 4), src + j * 8);
        }
    };

    const uint32_t bones[2] = {0x3C003C00u, 0x3C003C00u};  // f16 ones

    load_chunk(0, list[0] * 128);
    asm volatile("cp.async.commit_group;" ::: "memory");

    for (int t = 0; t < n; t++) {
        const int kc = list[t];
        const int kmin = kc * 128;
        const int st = t & 1;
        if (t + 1 < n) {
            load_chunk((t + 1) & 1, list[t + 1] * 128);
            asm volatile("cp.async.commit_group;" ::: "memory");
            asm volatile("cp.async.wait_group 1;" ::: "memory");
        } else {
            asm volatile("cp.async.wait_group 0;" ::: "memory");
        }
        __syncthreads();

        const char* kp = asmem + st * AST_B;
        const uint32_t vsb = abase + st * AST_B + AKS_B;

        // QK^T (bf16), scores arrive already in log2 units (q pre-scaled)
        float sc[16][4];
#pragma unroll
        for (int ni = 0; ni < 16; ni++) {
            sc[ni][0] = sc[ni][1] = sc[ni][2] = sc[ni][3] = 0.f;
            uint32_t bfr[2];
            const char* p = kp + (ni * 8 + gid) * 48 + tig * 4;
            bfr[0] = *(const uint32_t*)p;
            bfr[1] = *(const uint32_t*)(p + 16);
            mma16816(sc[ni], qa, bfr);
        }

        float rmax0 = -1e30f, rmax1 = -1e30f;
        if (kc < qch) {
            // fully visible chunk: bias only, no mask
            float b0 = sp_l2 * (float)(kmin + tig * 2 - i0);
            float b1 = b0 + sp_l2;
            float b2 = b0 - 8.f * sp_l2;
            float b3 = b2 + sp_l2;
            const float d8 = 8.f * sp_l2;
#pragma unroll
            for (int ni = 0; ni < 16; ni++) {
                sc[ni][0] += b0; sc[ni][1] += b1; sc[ni][2] += b2; sc[ni][3] += b3;
                rmax0 = fmaxf(rmax0, fmaxf(sc[ni][0], sc[ni][1]));
                rmax1 = fmaxf(rmax1, fmaxf(sc[ni][2], sc[ni][3]));
                b0 += d8; b1 += d8; b2 += d8; b3 += d8;
            }
        } else {
            // diagonal / override chunk: general mask
#pragma unroll
            for (int ni = 0; ni < 16; ni++) {
                int jc = kmin + ni * 8 + tig * 2;
#pragma unroll
                for (int r = 0; r < 4; r++) {
                    int j = jc + (r & 1);
                    int i = (r < 2) ? i0 : i1;
                    bool ok = (j <= i) || ((i >= fi) && (j >= li));
                    float s = ok ? fmaf(sp_l2, (float)(j - i), sc[ni][r]) : -1e30f;
                    sc[ni][r] = s;
                    if (r < 2) rmax0 = fmaxf(rmax0, s);
                    else rmax1 = fmaxf(rmax1, s);
                }
            }
        }
        rmax0 = fmaxf(rmax0, __shfl_xor_sync(0xffffffffu, rmax0, 1));
        rmax0 = fmaxf(rmax0, __shfl_xor_sync(0xffffffffu, rmax0, 2));
        rmax1 = fmaxf(rmax1, __shfl_xor_sync(0xffffffffu, rmax1, 1));
        rmax1 = fmaxf(rmax1, __shfl_xor_sync(0xffffffffu, rmax1, 2));
        float mn0 = fmaxf(m0, rmax0), mn1 = fmaxf(m1, rmax1);
        float cor0 = exp2f(m0 - mn0), cor1 = exp2f(m1 - mn1);
        m0 = mn0; m1 = mn1;
#pragma unroll
        for (int ni = 0; ni < 16; ni++) {
            o[ni][0] *= cor0; o[ni][1] *= cor0; o[ni][2] *= cor1; o[ni][3] *= cor1;
        }
        o_l[0] *= cor0; o_l[1] *= cor0; o_l[2] *= cor1; o_l[3] *= cor1;

        // P = exp2(s - m) directly as f16x2 fragments
        uint32_t pk0[16], pk1[16];
#pragma unroll
        for (int ni = 0; ni < 16; ni++) {
            pk0[ni] = exp2_f16x2(sc[ni][0] - m0, sc[ni][1] - m0);
            pk1[ni] = exp2_f16x2(sc[ni][2] - m1, sc[ni][3] - m1);
        }

        // PV (f16) + ones-column row sums
        const uint32_t vrow = vsb + l15 * 256;
#pragma unroll
        for (int ks = 0; ks < 8; ks++) {
            uint32_t pa[4] = {pk0[2 * ks], pk1[2 * ks], pk0[2 * ks + 1], pk1[2 * ks + 1]};
            mma16816h(o_l, pa, bones);
            const uint32_t kofs = vrow + ks * 4096;
#pragma unroll
            for (int ni2 = 0; ni2 < 8; ni2++) {
                uint32_t rr[4];
                ldsm4t(rr, kofs + (((ni2 * 2 + lhi) ^ l15) << 4));
                uint32_t b0[2] = {rr[0], rr[1]};
                uint32_t b1[2] = {rr[2], rr[3]};
                mma16816h(o[2 * ni2], pa, b0);
                mma16816h(o[2 * ni2 + 1], pa, b1);
            }
        }
        __syncthreads();
    }

    float inv0 = 1.f / o_l[0], inv1 = 1.f / o_l[2];
#pragma unroll
    for (int ni = 0; ni < 16; ni++) {
        int col = 1024 + h * 128 + ni * 8 + tig * 2;
        *(__nv_bfloat162*)&concat[((size_t)(b * SS) + i0) * EXPD + col] =
            __floats2bfloat162_rn(o[ni][0] * inv0, o[ni][1] * inv0);
        *(__nv_bfloat162*)&concat[((size_t)(b * SS) + i1) * EXPD + col] =
            __floats2bfloat162_rn(o[ni][2] * inv1, o[ni][3] * inv1);
    }
}

// ---------------- launch ----------------
extern "C" void kernel_launch(void* const* d_in, const int* in_sizes, int n_in,
                              void* d_out, int out_size) {
    const float* x = (const float*)d_in[0];
    const float* norm_w = (const float*)d_in[1];
    const float* expand_w = (const float*)d_in[2];
    const float* project_w = (const float*)d_in[3];
    const float* pbm = (const float*)d_in[4];
    const int* fi = (const int*)d_in[5];
    const int* li = (const int*)d_in[6];
    float* out = (float*)d_out;

    void *p_xn, *p_qk, *p_concat, *p_v, *p_wexp, *p_wproj;
    cudaGetSymbolAddress(&p_xn, g_xn);
    cudaGetSymbolAddress(&p_qk, g_qk);
    cudaGetSymbolAddress(&p_concat, g_concat);
    cudaGetSymbolAddress(&p_v, g_v);
    cudaGetSymbolAddress(&p_wexp, g_wexp);
    cudaGetSymbolAddress(&p_wproj, g_wproj);
    __nv_bfloat16* xn = (__nv_bfloat16*)p_xn;
    __nv_bfloat16* qk = (__nv_bfloat16*)p_qk;
    __nv_bfloat16* concat = (__nv_bfloat16*)p_concat;
    __half* vb = (__half*)p_v;
    __nv_bfloat16* wexp = (__nv_bfloat16*)p_wexp;
    __nv_bfloat16* wproj = (__nv_bfloat16*)p_wproj;

    cudaFuncSetAttribute(gemm_bf16<0>, cudaFuncAttributeMaxDynamicSharedMemorySize, GSMEM_BYTES);
    cudaFuncSetAttribute(gemm_bf16<1>, cudaFuncAttributeMaxDynamicSharedMemorySize, GSMEM_BYTES);
    cudaFuncSetAttribute(attn_kernel, cudaFuncAttributeMaxDynamicSharedMemorySize, ATT_SMEM);

    // weights -> bf16
    cvt_exp_kernel<<<EOUT * (DD / 4) / 256, 256>>>(expand_w, wexp);
    cvt_kernel<<<(DD * EXPD / 4 + 255) / 256, 256>>>(project_w, wproj, DD * EXPD / 4);

    // layernorm
    ln_kernel<<<NROWS, 256>>>(x, norm_w, xn);

    // expand GEMM fused with geglu: writes qk buffer (q pre-scaled) + concat[:, :1024] + vbuf (f16)
    gemm_bf16<0><<<dim3(EOUT / 128, NROWS / 128), 256, GSMEM_BYTES>>>(
        xn, wexp, qk, concat, vb, nullptr, nullptr, DD);

    // attention -> concat[:, 1024:2048]
    attn_kernel<<<dim3(SS / 128, BB * HH), 256, ATT_SMEM>>>(qk, vb, concat, pbm, fi, li);

    // project GEMM + residual: out = concat @ wproj^T + x
    gemm_bf16<1><<<dim3(DD / 128, NROWS / 128), 256, GSMEM_BYTES>>>(
        concat, wproj, nullptr, nullptr, nullptr, x, out, EXPD);
}